// round 9
// baseline (speedup 1.0000x reference)
#include <cuda_runtime.h>
#include <cuda_bf16.h>
#include <mma.h>
#include <math.h>

using namespace nvcuda;

#define BB 1024
#define TT 128
#define NN 256
#define HH 128
#define GG 512
#define BM 7
#define NBLK 147
#define SM_K4 24        // k4 groups of w_hh^T in smem (k < 96); 8 in regs
#define KP 512          // A concat K' = hi(256) | lo(256); w single bf16
#define AP 528          // A smem row pitch (bf16)
#define BP 72           // B smem column pitch (bf16)

typedef unsigned long long ull;
typedef unsigned int u32;

// ---------------- scratch ----------------------------------------------------
__device__ float  g_a[BB * NN];
__device__ float4 g_whh4[32 * GG];
__device__ float  g_bias[GG];
__device__ float  g_xproj[(size_t)BB * TT * GG];
__device__ __nv_bfloat16 g_wbf[GG * NN];   // [j][k] bf16(w_ih)

// ---------------- helpers ----------------------------------------------------
__device__ __forceinline__ void fma2(ull& d, ull a, ull b) {
    asm("fma.rn.f32x2 %0, %1, %2, %0;" : "+l"(d) : "l"(a), "l"(b));
}
__device__ __forceinline__ float2 unpack2(ull v) {
    float2 f; asm("mov.b64 {%0,%1}, %2;" : "=f"(f.x), "=f"(f.y) : "l"(v)); return f;
}
__device__ __forceinline__ float fsig(float x) {
    float e = __expf(-x); return __fdividef(1.0f, 1.0f + e);
}
__device__ __forceinline__ float ftanh(float x) {
    float e = __expf(2.0f * x); return 1.0f - __fdividef(2.0f, e + 1.0f);
}

// ---------------------------------------------------------------------------
// Setup
// ---------------------------------------------------------------------------
__global__ void setup_kernel(const float* __restrict__ w_ih,
                             const float* __restrict__ w_hh,
                             const float* __restrict__ b_ih,
                             const float* __restrict__ b_hh) {
    int idx = blockIdx.x * blockDim.x + threadIdx.x;
    int stride = gridDim.x * blockDim.x;
    if (idx < GG) g_bias[idx] = b_ih[idx] + b_hh[idx];
    for (int i = idx; i < 32 * GG; i += stride) {
        int k4 = i >> 9, j = i & (GG - 1);
        const float* wr = w_hh + j * HH + 4 * k4;
        g_whh4[i] = make_float4(wr[0], wr[1], wr[2], wr[3]);
    }
    for (int i = idx; i < GG * NN; i += stride)
        g_wbf[i] = __float2bfloat16_rn(w_ih[i]);
}

// ---------------------------------------------------------------------------
// Attention (time-invariant softmax) — unchanged.
// ---------------------------------------------------------------------------
__global__ __launch_bounds__(256)
void attn_kernel(const float* __restrict__ x,
                 const float* __restrict__ attn_w,
                 const float* __restrict__ attn_b,
                 float* __restrict__ out_attn) {
    __shared__ float s_wx[TT];
    __shared__ float s_red[256];
    int b = blockIdx.x;
    int n = threadIdx.x;
    if (n < TT) s_wx[n] = attn_w[2 * HH + n];
    __syncthreads();

    const float* xb = x + (size_t)b * TT * NN + n;
    float feat = attn_b[0];
#pragma unroll 8
    for (int t = 0; t < TT; t++) feat = fmaf(xb[(size_t)t * NN], s_wx[t], feat);

    s_red[n] = feat;
    __syncthreads();
#pragma unroll
    for (int s = 128; s > 0; s >>= 1) {
        if (n < s) s_red[n] = fmaxf(s_red[n], s_red[n + s]);
        __syncthreads();
    }
    float m = s_red[0];
    __syncthreads();
    float e = expf(feat - m);
    s_red[n] = e;
    __syncthreads();
#pragma unroll
    for (int s = 128; s > 0; s >>= 1) {
        if (n < s) s_red[n] += s_red[n + s];
        __syncthreads();
    }
    float a = e / s_red[0];

    g_a[b * NN + n] = a;

    float* ob = out_attn + (size_t)b * TT * NN + n;
#pragma unroll 8
    for (int t = 0; t < TT; t++) ob[(size_t)t * NN] = a;
}

// ---------------------------------------------------------------------------
// xproj via wmma, 2-pass: [A_hi | A_lo] x [w_bf | w_bf] = A_exact * w_bf.
// 8 chunks of 64 k' (chunks 4-7 reuse the same B data as 0-3).
// ---------------------------------------------------------------------------
#define SMX_A  0
#define SMX_B  (128 * AP * 2)
#define SMX_SA (SMX_B + 2 * 128 * BP * 2)
#define XP_SMEM (SMX_SA + NN * 4)

__global__ __launch_bounds__(256, 1)
void xproj_wmma_kernel(const float* __restrict__ x, float* __restrict__ xp) {
    extern __shared__ char smem[];
    __nv_bfloat16* As = (__nv_bfloat16*)(smem + SMX_A);   // [128][AP]: hi|lo
    __nv_bfloat16* Bs = (__nv_bfloat16*)(smem + SMX_B);   // [2][128][BP]
    float* s_a = (float*)(smem + SMX_SA);

    int jt = blockIdx.x, b = blockIdx.y;
    int tid = threadIdx.x;
    int wid = tid >> 5;
    const float* xb = x + (size_t)b * TT * NN;

    if (tid < 64) ((float4*)s_a)[tid] = ((const float4*)(g_a + b * NN))[tid];
    __syncthreads();

#pragma unroll
    for (int it = 0; it < 16; it++) {
        int seg = tid + 256 * it;
        int t = seg >> 5;
        int k8 = (seg & 31) * 8;
        float4 x0 = *(const float4*)&xb[t * NN + k8];
        float4 x1 = *(const float4*)&xb[t * NN + k8 + 4];
        float4 a0 = *(const float4*)&s_a[k8];
        float4 a1 = *(const float4*)&s_a[k8 + 4];
        float v[8] = {x0.x * a0.x, x0.y * a0.y, x0.z * a0.z, x0.w * a0.w,
                      x1.x * a1.x, x1.y * a1.y, x1.z * a1.z, x1.w * a1.w};
        u32 hw[4], lw[4];
#pragma unroll
        for (int p = 0; p < 4; p++) {
            __nv_bfloat16 h0 = __float2bfloat16_rn(v[2 * p]);
            __nv_bfloat16 h1 = __float2bfloat16_rn(v[2 * p + 1]);
            __nv_bfloat16 l0 = __float2bfloat16_rn(v[2 * p] - __bfloat162float(h0));
            __nv_bfloat16 l1 = __float2bfloat16_rn(v[2 * p + 1] - __bfloat162float(h1));
            __nv_bfloat162 hp = __halves2bfloat162(h0, h1);
            __nv_bfloat162 lp = __halves2bfloat162(l0, l1);
            hw[p] = *(u32*)&hp; lw[p] = *(u32*)&lp;
        }
        *(uint4*)&As[t * AP + k8]       = make_uint4(hw[0], hw[1], hw[2], hw[3]);
        *(uint4*)&As[t * AP + 256 + k8] = make_uint4(lw[0], lw[1], lw[2], lw[3]);
    }

    uint4 rb[4];
#pragma unroll
    for (int it = 0; it < 4; it++) {
        int seg = tid + 256 * it;
        int j = seg >> 3, kl8 = (seg & 7) * 8;
        rb[it] = *(const uint4*)&g_wbf[(size_t)(jt * 128 + j) * NN + kl8];
    }

    int m0 = (wid >> 1) * 32;
    int n0 = (wid & 1) * 64;
    wmma::fragment<wmma::accumulator, 16, 16, 16, float> acc[2][4];
#pragma unroll
    for (int i = 0; i < 2; i++)
#pragma unroll
        for (int nn = 0; nn < 4; nn++) wmma::fill_fragment(acc[i][nn], 0.0f);

    __syncthreads();

    for (int c = 0; c < 8; c++) {
        __nv_bfloat16* Bc = Bs + (c & 1) * 128 * BP;
#pragma unroll
        for (int it = 0; it < 4; it++) {
            int seg = tid + 256 * it;
            int j = seg >> 3, kl8 = (seg & 7) * 8;
            *(uint4*)&Bc[j * BP + kl8] = rb[it];
        }
        __syncthreads();

        if (c < 7) {
            int kb = ((c + 1) & 3) * 64;
#pragma unroll
            for (int it = 0; it < 4; it++) {
                int seg = tid + 256 * it;
                int j = seg >> 3, kl8 = (seg & 7) * 8;
                rb[it] = *(const uint4*)&g_wbf[(size_t)(jt * 128 + j) * NN + kb + kl8];
            }
        }

        int a_off = c * 64;   // 0..255 = hi, 256..511 = lo (A layout matches)

#pragma unroll
        for (int ks = 0; ks < 4; ks++) {
            wmma::fragment<wmma::matrix_a, 16, 16, 16, __nv_bfloat16, wmma::row_major> af[2];
#pragma unroll
            for (int i = 0; i < 2; i++)
                wmma::load_matrix_sync(af[i], &As[(m0 + i * 16) * AP + a_off + ks * 16], AP);
#pragma unroll
            for (int nn = 0; nn < 4; nn++) {
                wmma::fragment<wmma::matrix_b, 16, 16, 16, __nv_bfloat16, wmma::col_major> bf;
                wmma::load_matrix_sync(bf, &Bc[(n0 + nn * 16) * BP + ks * 16], BP);
                wmma::mma_sync(acc[0][nn], af[0], bf, acc[0][nn]);
                wmma::mma_sync(acc[1][nn], af[1], bf, acc[1][nn]);
            }
        }
    }

#pragma unroll
    for (int i = 0; i < 2; i++)
#pragma unroll
        for (int nn = 0; nn < 4; nn++)
            wmma::store_matrix_sync(
                xp + ((size_t)b * TT + m0 + i * 16) * GG + jt * 128 + n0 + nn * 16,
                acc[i][nn], GG, wmma::mem_row_major);
}

// ---------------------------------------------------------------------------
// Recurrent LSTM v4: 512 threads = 2 k-groups x 256. Group 0 covers k4 0..15,
// group 1 covers k4 16..31 (16..23 smem, 24..31 regs). Each thread owns cols
// (gt, gt+256). Partials: group 0 -> s_g[r][j] (+bias+xproj), group 1 ->
// s_g[r][512+j]; epilogue sums both. 16 warps = 4/SMSP for latency hiding.
// ---------------------------------------------------------------------------
__global__ __launch_bounds__(512, 1)
void lstm_kernel(const float* __restrict__ xp,
                 const float* __restrict__ h0,
                 const float* __restrict__ c0,
                 float* __restrict__ out_enc) {
    extern __shared__ char smem_raw[];
    float4* ws  = (float4*)smem_raw;                     // [SM_K4][GG]
    float*  s_h = (float*)(smem_raw + SM_K4 * GG * 16);  // [BM][HH]
    float*  s_c = s_h + BM * HH;                         // [BM][HH]
    float*  s_g = s_c + BM * HH;                         // [BM][1024]

    int tid = threadIdx.x;
    int grp = tid >> 8;           // 0 or 1
    int gt  = tid & 255;
    int b0 = blockIdx.x * BM;
    int j0 = gt, j1 = gt + 256;

    for (int i = tid; i < SM_K4 * GG; i += 512) ws[i] = g_whh4[i];

    // group-1 register tail: k4 24..31 for both columns
    ulonglong2 wt0[8], wt1[8];
    if (grp == 1) {
#pragma unroll
        for (int q = 0; q < 8; q++) {
            wt0[q] = *(const ulonglong2*)&g_whh4[(SM_K4 + q) * GG + j0];
            wt1[q] = *(const ulonglong2*)&g_whh4[(SM_K4 + q) * GG + j1];
        }
    }

    for (int i = tid; i < BM * HH; i += 512) {
        int r = i >> 7, k = i & (HH - 1);
        int b = b0 + r;
        float hv = 0.f, cv = 0.f;
        if (b < BB) { hv = h0[(size_t)b * HH + k]; cv = c0[(size_t)b * HH + k]; }
        s_h[i] = hv; s_c[i] = cv;
    }
    float bias0 = 0.f, bias1 = 0.f;
    if (grp == 0) { bias0 = g_bias[j0]; bias1 = g_bias[j1]; }
    __syncthreads();

    const float* xrow[BM];
#pragma unroll
    for (int r = 0; r < BM; r++) {
        int b = b0 + r; if (b > BB - 1) b = BB - 1;
        xrow[r] = xp + (size_t)b * TT * GG;
    }

    const float4* wsj0 = ws + j0;
    const float4* wsj1 = ws + j1;
    const int lin = tid * 2;                       // epilogue: 2 cells, same row
    const int er = lin >> 7, ek = lin & (HH - 1);
    const bool eact = lin < BM * HH;
    const bool ewr  = eact && (b0 + er < BB);

    for (int t = 0; t < TT; t++) {
        float xpv0[BM], xpv1[BM];
        if (grp == 0) {
#pragma unroll
            for (int r = 0; r < BM; r++) {
                xpv0[r] = xrow[r][(size_t)t * GG + j0];
                xpv1[r] = xrow[r][(size_t)t * GG + j1];
            }
        }

        ull acc0[BM], acc1[BM];
#pragma unroll
        for (int r = 0; r < BM; r++) { acc0[r] = 0ULL; acc1[r] = 0ULL; }

        if (grp == 0) {
            // k4 0..15 from smem
#pragma unroll
            for (int k4 = 0; k4 < 16; k4++) {
                ulonglong2 w0 = *(const ulonglong2*)&wsj0[k4 * GG];
                ulonglong2 w1 = *(const ulonglong2*)&wsj1[k4 * GG];
#pragma unroll
                for (int r = 0; r < BM; r++) {
                    ulonglong2 hp = *(const ulonglong2*)&s_h[r * HH + k4 * 4];
                    fma2(acc0[r], hp.x, w0.x); fma2(acc0[r], hp.y, w0.y);
                    fma2(acc1[r], hp.x, w1.x); fma2(acc1[r], hp.y, w1.y);
                }
            }
        } else {
            // register tail k4 24..31 first
#pragma unroll
            for (int q = 0; q < 8; q++) {
#pragma unroll
                for (int r = 0; r < BM; r++) {
                    ulonglong2 hp = *(const ulonglong2*)&s_h[r * HH + (SM_K4 + q) * 4];
                    fma2(acc0[r], hp.x, wt0[q].x); fma2(acc0[r], hp.y, wt0[q].y);
                    fma2(acc1[r], hp.x, wt1[q].x); fma2(acc1[r], hp.y, wt1[q].y);
                }
            }
            // k4 16..23 from smem
#pragma unroll
            for (int k4 = 16; k4 < 24; k4++) {
                ulonglong2 w0 = *(const ulonglong2*)&wsj0[k4 * GG];
                ulonglong2 w1 = *(const ulonglong2*)&wsj1[k4 * GG];
#pragma unroll
                for (int r = 0; r < BM; r++) {
                    ulonglong2 hp = *(const ulonglong2*)&s_h[r * HH + k4 * 4];
                    fma2(acc0[r], hp.x, w0.x); fma2(acc0[r], hp.y, w0.y);
                    fma2(acc1[r], hp.x, w1.x); fma2(acc1[r], hp.y, w1.y);
                }
            }
        }

        if (grp == 0) {
#pragma unroll
            for (int r = 0; r < BM; r++) {
                float2 p0 = unpack2(acc0[r]);
                float2 p1 = unpack2(acc1[r]);
                s_g[r * 1024 + j0] = p0.x + p0.y + bias0 + xpv0[r];
                s_g[r * 1024 + j1] = p1.x + p1.y + bias1 + xpv1[r];
            }
        } else {
#pragma unroll
            for (int r = 0; r < BM; r++) {
                float2 p0 = unpack2(acc0[r]);
                float2 p1 = unpack2(acc1[r]);
                s_g[r * 1024 + 512 + j0] = p0.x + p0.y;
                s_g[r * 1024 + 512 + j1] = p1.x + p1.y;
            }
        }
        __syncthreads();

        // epilogue: thread owns cells (er, ek..ek+1); gate = part0 + part1
        if (eact) {
            const float* gr = &s_g[er * 1024];
            float2 gi0 = *(const float2*)&gr[ek];
            float2 gi1 = *(const float2*)&gr[512 + ek];
            float2 gf0 = *(const float2*)&gr[HH + ek];
            float2 gf1 = *(const float2*)&gr[512 + HH + ek];
            float2 gg0 = *(const float2*)&gr[2 * HH + ek];
            float2 gg1 = *(const float2*)&gr[512 + 2 * HH + ek];
            float2 go0 = *(const float2*)&gr[3 * HH + ek];
            float2 go1 = *(const float2*)&gr[512 + 3 * HH + ek];
            float2 cc  = *(const float2*)&s_c[er * HH + ek];

            float i0 = fsig(gi0.x + gi1.x), i1 = fsig(gi0.y + gi1.y);
            float f0 = fsig(gf0.x + gf1.x), f1 = fsig(gf0.y + gf1.y);
            float g0 = ftanh(gg0.x + gg1.x), g1 = ftanh(gg0.y + gg1.y);
            float o0 = fsig(go0.x + go1.x), o1 = fsig(go0.y + go1.y);

            float c0n = fmaf(f0, cc.x, i0 * g0);
            float c1n = fmaf(f1, cc.y, i1 * g1);
            float h0n = o0 * ftanh(c0n);
            float h1n = o1 * ftanh(c1n);

            *(float2*)&s_c[er * HH + ek] = make_float2(c0n, c1n);
            *(float2*)&s_h[er * HH + ek] = make_float2(h0n, h1n);
            if (ewr)
                *(float2*)(out_enc + ((size_t)(b0 + er) * TT + t) * HH + ek) =
                    make_float2(h0n, h1n);
        }
        __syncthreads();
    }
}

// ---------------------------------------------------------------------------
// Launch
// ---------------------------------------------------------------------------
extern "C" void kernel_launch(void* const* d_in, const int* in_sizes, int n_in,
                              void* d_out, int out_size) {
    const float* x      = (const float*)d_in[0];
    const float* attn_w = (const float*)d_in[1];
    const float* attn_b = (const float*)d_in[2];
    const float* w_ih   = (const float*)d_in[3];
    const float* w_hh   = (const float*)d_in[4];
    const float* b_ih   = (const float*)d_in[5];
    const float* b_hh   = (const float*)d_in[6];
    const float* h0     = (const float*)d_in[7];
    const float* c0     = (const float*)d_in[8];

    float* out      = (float*)d_out;
    float* out_attn = out;
    float* out_enc  = out + (size_t)BB * TT * NN;

    float* xproj;
    cudaGetSymbolAddress((void**)&xproj, g_xproj);

    // weights 196608 + h/c 7168 + gates 28672 = 232448? No: 196608+3584*2+28672 = 232448
    // -> over 227KB; gates are [BM][1024] = 28672, h+c = 7168, weights 196608: trim via SM_K4=24 exact:
    int lstm_smem = SM_K4 * GG * 16 + BM * HH * 4 * 2 + BM * 1024 * 4;
    cudaFuncSetAttribute(lstm_kernel,
                         cudaFuncAttributeMaxDynamicSharedMemorySize, 232448);
    cudaFuncSetAttribute(xproj_wmma_kernel,
                         cudaFuncAttributeMaxDynamicSharedMemorySize, XP_SMEM);

    setup_kernel<<<192, 256>>>(w_ih, w_hh, b_ih, b_hh);
    attn_kernel<<<BB, 256>>>(x, attn_w, attn_b, out_attn);
    xproj_wmma_kernel<<<dim3(4, BB), 256, XP_SMEM>>>(x, xproj);
    lstm_kernel<<<NBLK, 512, lstm_smem>>>(xproj, h0, c0, out_enc);
}

// round 10
// speedup vs baseline: 1.1031x; 1.1031x over previous
#include <cuda_runtime.h>
#include <cuda_bf16.h>
#include <mma.h>
#include <math.h>

using namespace nvcuda;

#define BB 1024
#define TT 128
#define NN 256
#define HH 128
#define GG 512
#define BM 7
#define NBLK 147
#define SM_K4 22        // k4 groups of w_hh^T in smem (k < 88); 10 in regs
#define AP 528          // A smem row pitch (bf16)
#define BP 72           // B smem column pitch (bf16)

typedef unsigned long long ull;
typedef unsigned int u32;

// ---------------- scratch ----------------------------------------------------
__device__ float  g_a[BB * NN];
__device__ float4 g_whh4[32 * GG];
__device__ float  g_bias[GG];
__device__ float  g_xproj[(size_t)BB * TT * GG];
__device__ __nv_bfloat16 g_wbf[GG * NN];   // [j][k] bf16(w_ih)

// ---------------- helpers ----------------------------------------------------
__device__ __forceinline__ void fma2(ull& d, ull a, ull b) {
    asm("fma.rn.f32x2 %0, %1, %2, %0;" : "+l"(d) : "l"(a), "l"(b));
}
__device__ __forceinline__ float2 unpack2(ull v) {
    float2 f; asm("mov.b64 {%0,%1}, %2;" : "=f"(f.x), "=f"(f.y) : "l"(v)); return f;
}
__device__ __forceinline__ float fsig(float x) {
    float e = __expf(-x); return __fdividef(1.0f, 1.0f + e);
}
__device__ __forceinline__ float ftanh(float x) {
    float e = __expf(2.0f * x); return 1.0f - __fdividef(2.0f, e + 1.0f);
}

// ---------------------------------------------------------------------------
// Setup
// ---------------------------------------------------------------------------
__global__ void setup_kernel(const float* __restrict__ w_ih,
                             const float* __restrict__ w_hh,
                             const float* __restrict__ b_ih,
                             const float* __restrict__ b_hh) {
    int idx = blockIdx.x * blockDim.x + threadIdx.x;
    int stride = gridDim.x * blockDim.x;
    if (idx < GG) g_bias[idx] = b_ih[idx] + b_hh[idx];
    for (int i = idx; i < 32 * GG; i += stride) {
        int k4 = i >> 9, j = i & (GG - 1);
        const float* wr = w_hh + j * HH + 4 * k4;
        g_whh4[i] = make_float4(wr[0], wr[1], wr[2], wr[3]);
    }
    for (int i = idx; i < GG * NN; i += stride)
        g_wbf[i] = __float2bfloat16_rn(w_ih[i]);
}

// ---------------------------------------------------------------------------
// Attention (time-invariant softmax).
// ---------------------------------------------------------------------------
__global__ __launch_bounds__(256)
void attn_kernel(const float* __restrict__ x,
                 const float* __restrict__ attn_w,
                 const float* __restrict__ attn_b,
                 float* __restrict__ out_attn) {
    __shared__ float s_wx[TT];
    __shared__ float s_red[256];
    int b = blockIdx.x;
    int n = threadIdx.x;
    if (n < TT) s_wx[n] = attn_w[2 * HH + n];
    __syncthreads();

    const float* xb = x + (size_t)b * TT * NN + n;
    float feat = attn_b[0];
#pragma unroll 8
    for (int t = 0; t < TT; t++) feat = fmaf(xb[(size_t)t * NN], s_wx[t], feat);

    s_red[n] = feat;
    __syncthreads();
#pragma unroll
    for (int s = 128; s > 0; s >>= 1) {
        if (n < s) s_red[n] = fmaxf(s_red[n], s_red[n + s]);
        __syncthreads();
    }
    float m = s_red[0];
    __syncthreads();
    float e = expf(feat - m);
    s_red[n] = e;
    __syncthreads();
#pragma unroll
    for (int s = 128; s > 0; s >>= 1) {
        if (n < s) s_red[n] += s_red[n + s];
        __syncthreads();
    }
    float a = e / s_red[0];

    g_a[b * NN + n] = a;

    float* ob = out_attn + (size_t)b * TT * NN + n;
#pragma unroll 8
    for (int t = 0; t < TT; t++) ob[(size_t)t * NN] = a;
}

// ---------------------------------------------------------------------------
// xproj via wmma, 2-pass: [A_hi | A_lo] x [w_bf | w_bf] = A_exact * w_bf.
// (unchanged from R8 — confirmed working, ~160us)
// ---------------------------------------------------------------------------
#define SMX_A  0
#define SMX_B  (128 * AP * 2)
#define SMX_SA (SMX_B + 2 * 128 * BP * 2)
#define XP_SMEM (SMX_SA + NN * 4)

__global__ __launch_bounds__(256, 1)
void xproj_wmma_kernel(const float* __restrict__ x, float* __restrict__ xp) {
    extern __shared__ char smem[];
    __nv_bfloat16* As = (__nv_bfloat16*)(smem + SMX_A);   // [128][AP]: hi|lo
    __nv_bfloat16* Bs = (__nv_bfloat16*)(smem + SMX_B);   // [2][128][BP]
    float* s_a = (float*)(smem + SMX_SA);

    int jt = blockIdx.x, b = blockIdx.y;
    int tid = threadIdx.x;
    int wid = tid >> 5;
    const float* xb = x + (size_t)b * TT * NN;

    if (tid < 64) ((float4*)s_a)[tid] = ((const float4*)(g_a + b * NN))[tid];
    __syncthreads();

#pragma unroll
    for (int it = 0; it < 16; it++) {
        int seg = tid + 256 * it;
        int t = seg >> 5;
        int k8 = (seg & 31) * 8;
        float4 x0 = *(const float4*)&xb[t * NN + k8];
        float4 x1 = *(const float4*)&xb[t * NN + k8 + 4];
        float4 a0 = *(const float4*)&s_a[k8];
        float4 a1 = *(const float4*)&s_a[k8 + 4];
        float v[8] = {x0.x * a0.x, x0.y * a0.y, x0.z * a0.z, x0.w * a0.w,
                      x1.x * a1.x, x1.y * a1.y, x1.z * a1.z, x1.w * a1.w};
        u32 hw[4], lw[4];
#pragma unroll
        for (int p = 0; p < 4; p++) {
            __nv_bfloat16 h0 = __float2bfloat16_rn(v[2 * p]);
            __nv_bfloat16 h1 = __float2bfloat16_rn(v[2 * p + 1]);
            __nv_bfloat16 l0 = __float2bfloat16_rn(v[2 * p] - __bfloat162float(h0));
            __nv_bfloat16 l1 = __float2bfloat16_rn(v[2 * p + 1] - __bfloat162float(h1));
            __nv_bfloat162 hp = __halves2bfloat162(h0, h1);
            __nv_bfloat162 lp = __halves2bfloat162(l0, l1);
            hw[p] = *(u32*)&hp; lw[p] = *(u32*)&lp;
        }
        *(uint4*)&As[t * AP + k8]       = make_uint4(hw[0], hw[1], hw[2], hw[3]);
        *(uint4*)&As[t * AP + 256 + k8] = make_uint4(lw[0], lw[1], lw[2], lw[3]);
    }

    uint4 rb[4];
#pragma unroll
    for (int it = 0; it < 4; it++) {
        int seg = tid + 256 * it;
        int j = seg >> 3, kl8 = (seg & 7) * 8;
        rb[it] = *(const uint4*)&g_wbf[(size_t)(jt * 128 + j) * NN + kl8];
    }

    int m0 = (wid >> 1) * 32;
    int n0 = (wid & 1) * 64;
    wmma::fragment<wmma::accumulator, 16, 16, 16, float> acc[2][4];
#pragma unroll
    for (int i = 0; i < 2; i++)
#pragma unroll
        for (int nn = 0; nn < 4; nn++) wmma::fill_fragment(acc[i][nn], 0.0f);

    __syncthreads();

    for (int c = 0; c < 8; c++) {
        __nv_bfloat16* Bc = Bs + (c & 1) * 128 * BP;
#pragma unroll
        for (int it = 0; it < 4; it++) {
            int seg = tid + 256 * it;
            int j = seg >> 3, kl8 = (seg & 7) * 8;
            *(uint4*)&Bc[j * BP + kl8] = rb[it];
        }
        __syncthreads();

        if (c < 7) {
            int kb = ((c + 1) & 3) * 64;
#pragma unroll
            for (int it = 0; it < 4; it++) {
                int seg = tid + 256 * it;
                int j = seg >> 3, kl8 = (seg & 7) * 8;
                rb[it] = *(const uint4*)&g_wbf[(size_t)(jt * 128 + j) * NN + kb + kl8];
            }
        }

        int a_off = c * 64;   // 0..255 = hi, 256..511 = lo

#pragma unroll
        for (int ks = 0; ks < 4; ks++) {
            wmma::fragment<wmma::matrix_a, 16, 16, 16, __nv_bfloat16, wmma::row_major> af[2];
#pragma unroll
            for (int i = 0; i < 2; i++)
                wmma::load_matrix_sync(af[i], &As[(m0 + i * 16) * AP + a_off + ks * 16], AP);
#pragma unroll
            for (int nn = 0; nn < 4; nn++) {
                wmma::fragment<wmma::matrix_b, 16, 16, 16, __nv_bfloat16, wmma::col_major> bf;
                wmma::load_matrix_sync(bf, &Bc[(n0 + nn * 16) * BP + ks * 16], BP);
                wmma::mma_sync(acc[0][nn], af[0], bf, acc[0][nn]);
                wmma::mma_sync(acc[1][nn], af[1], bf, acc[1][nn]);
            }
        }
    }

#pragma unroll
    for (int i = 0; i < 2; i++)
#pragma unroll
        for (int nn = 0; nn < 4; nn++)
            wmma::store_matrix_sync(
                xp + ((size_t)b * TT + m0 + i * 16) * GG + jt * 128 + n0 + nn * 16,
                acc[i][nn], GG, wmma::mem_row_major);
}

// ---------------------------------------------------------------------------
// Recurrent LSTM (R7 winner, reverted): 256 threads, 2 gate columns per
// thread (j, j+256). k<88 weights in smem, k>=88 (10 k4 groups) in regs.
// ---------------------------------------------------------------------------
__global__ __launch_bounds__(256, 1)
void lstm_kernel(const float* __restrict__ xp,
                 const float* __restrict__ h0,
                 const float* __restrict__ c0,
                 float* __restrict__ out_enc) {
    extern __shared__ char smem_raw[];
    float4* ws  = (float4*)smem_raw;                     // [SM_K4][GG]
    float*  s_h = (float*)(smem_raw + SM_K4 * GG * 16);  // [BM][HH]
    float*  s_c = s_h + BM * HH;                         // [BM][HH]
    float*  s_g = s_c + BM * HH;                         // [BM][GG]

    int tid = threadIdx.x;
    int b0 = blockIdx.x * BM;
    int j0 = tid, j1 = tid + 256;

    for (int i = tid; i < SM_K4 * GG; i += 256) ws[i] = g_whh4[i];

    // tail weights (k4 = SM_K4..31) in registers for BOTH columns
    ulonglong2 wt0[32 - SM_K4], wt1[32 - SM_K4];
#pragma unroll
    for (int q = 0; q < 32 - SM_K4; q++) {
        wt0[q] = *(const ulonglong2*)&g_whh4[(SM_K4 + q) * GG + j0];
        wt1[q] = *(const ulonglong2*)&g_whh4[(SM_K4 + q) * GG + j1];
    }

    for (int i = tid; i < BM * HH; i += 256) {
        int r = i >> 7, k = i & (HH - 1);
        int b = b0 + r;
        float hv = 0.f, cv = 0.f;
        if (b < BB) { hv = h0[(size_t)b * HH + k]; cv = c0[(size_t)b * HH + k]; }
        s_h[i] = hv; s_c[i] = cv;
    }
    float bias0 = g_bias[j0], bias1 = g_bias[j1];
    __syncthreads();

    const float* xrow[BM];
#pragma unroll
    for (int r = 0; r < BM; r++) {
        int b = b0 + r; if (b > BB - 1) b = BB - 1;
        xrow[r] = xp + (size_t)b * TT * GG;
    }

    const float4* wsj0 = ws + j0;
    const float4* wsj1 = ws + j1;
    const int lin = tid * 4;                       // epilogue: 4 cells, same row
    const int er = lin >> 7, ek = lin & (HH - 1);
    const bool eact = lin < BM * HH;
    const bool ewr  = eact && (b0 + er < BB);

    for (int t = 0; t < TT; t++) {
        // prefetch xproj for this step (consumed after the matvec)
        float xpv0[BM], xpv1[BM];
#pragma unroll
        for (int r = 0; r < BM; r++) {
            xpv0[r] = xrow[r][(size_t)t * GG + j0];
            xpv1[r] = xrow[r][(size_t)t * GG + j1];
        }

        ull acc0[BM], acc1[BM];
#pragma unroll
        for (int r = 0; r < BM; r++) { acc0[r] = 0ULL; acc1[r] = 0ULL; }

        // register-resident tail first (zero smem weight traffic)
#pragma unroll
        for (int q = 0; q < 32 - SM_K4; q++) {
#pragma unroll
            for (int r = 0; r < BM; r++) {
                ulonglong2 hp = *(const ulonglong2*)&s_h[r * HH + (SM_K4 + q) * 4];
                fma2(acc0[r], hp.x, wt0[q].x); fma2(acc0[r], hp.y, wt0[q].y);
                fma2(acc1[r], hp.x, wt1[q].x); fma2(acc1[r], hp.y, wt1[q].y);
            }
        }
        // smem-resident body (k4 0..SM_K4-1)
#pragma unroll
        for (int k4 = 0; k4 < SM_K4; k4++) {
            ulonglong2 w0 = *(const ulonglong2*)&wsj0[k4 * GG];
            ulonglong2 w1 = *(const ulonglong2*)&wsj1[k4 * GG];
#pragma unroll
            for (int r = 0; r < BM; r++) {
                ulonglong2 hp = *(const ulonglong2*)&s_h[r * HH + k4 * 4];
                fma2(acc0[r], hp.x, w0.x); fma2(acc0[r], hp.y, w0.y);
                fma2(acc1[r], hp.x, w1.x); fma2(acc1[r], hp.y, w1.y);
            }
        }

#pragma unroll
        for (int r = 0; r < BM; r++) {
            float2 p0 = unpack2(acc0[r]);
            float2 p1 = unpack2(acc1[r]);
            s_g[r * GG + j0] = p0.x + p0.y + bias0 + xpv0[r];
            s_g[r * GG + j1] = p1.x + p1.y + bias1 + xpv1[r];
        }
        __syncthreads();

        // gate activations + state update: thread owns cells (er, ek..ek+3)
        if (eact) {
            float4 gi = *(const float4*)&s_g[er * GG + ek];
            float4 gf = *(const float4*)&s_g[er * GG + HH + ek];
            float4 gg = *(const float4*)&s_g[er * GG + 2 * HH + ek];
            float4 go = *(const float4*)&s_g[er * GG + 3 * HH + ek];
            float4 cc = *(const float4*)&s_c[er * HH + ek];

            float gI[4] = {gi.x, gi.y, gi.z, gi.w};
            float gF[4] = {gf.x, gf.y, gf.z, gf.w};
            float gGv[4] = {gg.x, gg.y, gg.z, gg.w};
            float gO[4] = {go.x, go.y, go.z, go.w};
            float cC[4] = {cc.x, cc.y, cc.z, cc.w};
            float hn[4], cn[4];
#pragma unroll
            for (int l = 0; l < 4; l++) {
                float iv = fsig(gI[l]);
                float fv = fsig(gF[l]);
                float gv = ftanh(gGv[l]);
                float ov = fsig(gO[l]);
                cn[l] = fmaf(fv, cC[l], iv * gv);
                hn[l] = ov * ftanh(cn[l]);
            }
            *(float4*)&s_c[er * HH + ek] = make_float4(cn[0], cn[1], cn[2], cn[3]);
            *(float4*)&s_h[er * HH + ek] = make_float4(hn[0], hn[1], hn[2], hn[3]);
            if (ewr)
                *(float4*)(out_enc + ((size_t)(b0 + er) * TT + t) * HH + ek) =
                    make_float4(hn[0], hn[1], hn[2], hn[3]);
        }
        __syncthreads();
    }
}

// ---------------------------------------------------------------------------
// Launch
// ---------------------------------------------------------------------------
extern "C" void kernel_launch(void* const* d_in, const int* in_sizes, int n_in,
                              void* d_out, int out_size) {
    const float* x      = (const float*)d_in[0];
    const float* attn_w = (const float*)d_in[1];
    const float* attn_b = (const float*)d_in[2];
    const float* w_ih   = (const float*)d_in[3];
    const float* w_hh   = (const float*)d_in[4];
    const float* b_ih   = (const float*)d_in[5];
    const float* b_hh   = (const float*)d_in[6];
    const float* h0     = (const float*)d_in[7];
    const float* c0     = (const float*)d_in[8];

    float* out      = (float*)d_out;
    float* out_attn = out;
    float* out_enc  = out + (size_t)BB * TT * NN;

    float* xproj;
    cudaGetSymbolAddress((void**)&xproj, g_xproj);

    int lstm_smem = SM_K4 * GG * 16 + BM * HH * 4 * 2 + BM * GG * 4;  // 201728
    cudaFuncSetAttribute(lstm_kernel,
                         cudaFuncAttributeMaxDynamicSharedMemorySize, lstm_smem);
    cudaFuncSetAttribute(xproj_wmma_kernel,
                         cudaFuncAttributeMaxDynamicSharedMemorySize, XP_SMEM);

    setup_kernel<<<192, 256>>>(w_ih, w_hh, b_ih, b_hh);
    attn_kernel<<<BB, 256>>>(x, attn_w, attn_b, out_attn);
    xproj_wmma_kernel<<<dim3(4, BB), 256, XP_SMEM>>>(x, xproj);
    lstm_kernel<<<NBLK, 256, lstm_smem>>>(xproj, h0, c0, out_enc);
}

// round 11
// speedup vs baseline: 1.4147x; 1.2825x over previous
#include <cuda_runtime.h>
#include <cuda_bf16.h>
#include <mma.h>
#include <math.h>

using namespace nvcuda;

#define BB 1024
#define TT 128
#define NN 256
#define HH 128
#define GG 512
#define BM 7
#define NBLK 147
#define SM_K4 22        // k4 groups of w_hh^T in smem (k < 88); 10 in regs
#define AP 264          // A smem row pitch (bf16): 256 + 8 pad
#define BP 72           // B smem column pitch (bf16)

typedef unsigned long long ull;
typedef unsigned int u32;

// ---------------- scratch ----------------------------------------------------
__device__ float  g_a[BB * NN];
__device__ float4 g_whh4[32 * GG];
__device__ float  g_bias[GG];
__device__ float  g_xproj[(size_t)BB * TT * GG];
__device__ __nv_bfloat16 g_wbf[GG * NN];   // [j][k] bf16(w_ih)

// ---------------- helpers ----------------------------------------------------
__device__ __forceinline__ void fma2(ull& d, ull a, ull b) {
    asm("fma.rn.f32x2 %0, %1, %2, %0;" : "+l"(d) : "l"(a), "l"(b));
}
__device__ __forceinline__ float2 unpack2(ull v) {
    float2 f; asm("mov.b64 {%0,%1}, %2;" : "=f"(f.x), "=f"(f.y) : "l"(v)); return f;
}
__device__ __forceinline__ float fsig(float x) {
    float e = __expf(-x); return __fdividef(1.0f, 1.0f + e);
}
__device__ __forceinline__ float ftanh(float x) {
    float e = __expf(2.0f * x); return 1.0f - __fdividef(2.0f, e + 1.0f);
}

// ---------------------------------------------------------------------------
// Setup
// ---------------------------------------------------------------------------
__global__ void setup_kernel(const float* __restrict__ w_ih,
                             const float* __restrict__ w_hh,
                             const float* __restrict__ b_ih,
                             const float* __restrict__ b_hh) {
    int idx = blockIdx.x * blockDim.x + threadIdx.x;
    int stride = gridDim.x * blockDim.x;
    if (idx < GG) g_bias[idx] = b_ih[idx] + b_hh[idx];
    for (int i = idx; i < 32 * GG; i += stride) {
        int k4 = i >> 9, j = i & (GG - 1);
        const float* wr = w_hh + j * HH + 4 * k4;
        g_whh4[i] = make_float4(wr[0], wr[1], wr[2], wr[3]);
    }
    for (int i = idx; i < GG * NN; i += stride)
        g_wbf[i] = __float2bfloat16_rn(w_ih[i]);
}

// ---------------------------------------------------------------------------
// Attention (time-invariant softmax).
// ---------------------------------------------------------------------------
__global__ __launch_bounds__(256)
void attn_kernel(const float* __restrict__ x,
                 const float* __restrict__ attn_w,
                 const float* __restrict__ attn_b,
                 float* __restrict__ out_attn) {
    __shared__ float s_wx[TT];
    __shared__ float s_red[256];
    int b = blockIdx.x;
    int n = threadIdx.x;
    if (n < TT) s_wx[n] = attn_w[2 * HH + n];
    __syncthreads();

    const float* xb = x + (size_t)b * TT * NN + n;
    float feat = attn_b[0];
#pragma unroll 8
    for (int t = 0; t < TT; t++) feat = fmaf(xb[(size_t)t * NN], s_wx[t], feat);

    s_red[n] = feat;
    __syncthreads();
#pragma unroll
    for (int s = 128; s > 0; s >>= 1) {
        if (n < s) s_red[n] = fmaxf(s_red[n], s_red[n + s]);
        __syncthreads();
    }
    float m = s_red[0];
    __syncthreads();
    float e = expf(feat - m);
    s_red[n] = e;
    __syncthreads();
#pragma unroll
    for (int s = 128; s > 0; s >>= 1) {
        if (n < s) s_red[n] += s_red[n + s];
        __syncthreads();
    }
    float a = e / s_red[0];

    g_a[b * NN + n] = a;

    float* ob = out_attn + (size_t)b * TT * NN + n;
#pragma unroll 8
    for (int t = 0; t < TT; t++) ob[(size_t)t * NN] = a;
}

// ---------------------------------------------------------------------------
// xproj via wmma, 1-pass bf16: bf16(a*x) @ bf16(w_ih^T), fp32 accum.
// K = 256, 4 chunks of 64. 2 CTAs/SM (105.5 KB smem) — A-build of one CTA
// hides under the other's HMMA.
// ---------------------------------------------------------------------------
#define SMX_A  0
#define SMX_B  (128 * AP * 2)                  // 67584
#define SMX_SA (SMX_B + 2 * 128 * BP * 2)      // 104448
#define XP_SMEM (SMX_SA + NN * 4)              // 105472

__global__ __launch_bounds__(256, 2)
void xproj_wmma_kernel(const float* __restrict__ x, float* __restrict__ xp) {
    extern __shared__ char smem[];
    __nv_bfloat16* As = (__nv_bfloat16*)(smem + SMX_A);   // [128][AP]
    __nv_bfloat16* Bs = (__nv_bfloat16*)(smem + SMX_B);   // [2][128][BP]
    float* s_a = (float*)(smem + SMX_SA);

    int jt = blockIdx.x, b = blockIdx.y;
    int tid = threadIdx.x;
    int wid = tid >> 5;
    const float* xb = x + (size_t)b * TT * NN;

    if (tid < 64) ((float4*)s_a)[tid] = ((const float4*)(g_a + b * NN))[tid];
    __syncthreads();

    // build A = bf16(a * x): 4096 segs of 8 elems, 16 per thread
#pragma unroll
    for (int it = 0; it < 16; it++) {
        int seg = tid + 256 * it;
        int t = seg >> 5;
        int k8 = (seg & 31) * 8;
        float4 x0 = *(const float4*)&xb[t * NN + k8];
        float4 x1 = *(const float4*)&xb[t * NN + k8 + 4];
        float4 a0 = *(const float4*)&s_a[k8];
        float4 a1 = *(const float4*)&s_a[k8 + 4];
        float v[8] = {x0.x * a0.x, x0.y * a0.y, x0.z * a0.z, x0.w * a0.w,
                      x1.x * a1.x, x1.y * a1.y, x1.z * a1.z, x1.w * a1.w};
        u32 hw[4];
#pragma unroll
        for (int p = 0; p < 4; p++) {
            __nv_bfloat162 hp = __halves2bfloat162(
                __float2bfloat16_rn(v[2 * p]), __float2bfloat16_rn(v[2 * p + 1]));
            hw[p] = *(u32*)&hp;
        }
        *(uint4*)&As[t * AP + k8] = make_uint4(hw[0], hw[1], hw[2], hw[3]);
    }

    // prefetch B chunk 0
    uint4 rb[4];
#pragma unroll
    for (int it = 0; it < 4; it++) {
        int seg = tid + 256 * it;
        int j = seg >> 3, kl8 = (seg & 7) * 8;
        rb[it] = *(const uint4*)&g_wbf[(size_t)(jt * 128 + j) * NN + kl8];
    }

    int m0 = (wid >> 1) * 32;
    int n0 = (wid & 1) * 64;
    wmma::fragment<wmma::accumulator, 16, 16, 16, float> acc[2][4];
#pragma unroll
    for (int i = 0; i < 2; i++)
#pragma unroll
        for (int nn = 0; nn < 4; nn++) wmma::fill_fragment(acc[i][nn], 0.0f);

    __syncthreads();

    for (int c = 0; c < 4; c++) {
        __nv_bfloat16* Bc = Bs + (c & 1) * 128 * BP;
#pragma unroll
        for (int it = 0; it < 4; it++) {
            int seg = tid + 256 * it;
            int j = seg >> 3, kl8 = (seg & 7) * 8;
            *(uint4*)&Bc[j * BP + kl8] = rb[it];
        }
        __syncthreads();

        if (c < 3) {
            int kb = (c + 1) * 64;
#pragma unroll
            for (int it = 0; it < 4; it++) {
                int seg = tid + 256 * it;
                int j = seg >> 3, kl8 = (seg & 7) * 8;
                rb[it] = *(const uint4*)&g_wbf[(size_t)(jt * 128 + j) * NN + kb + kl8];
            }
        }

        int a_off = c * 64;

#pragma unroll
        for (int ks = 0; ks < 4; ks++) {
            wmma::fragment<wmma::matrix_a, 16, 16, 16, __nv_bfloat16, wmma::row_major> af[2];
#pragma unroll
            for (int i = 0; i < 2; i++)
                wmma::load_matrix_sync(af[i], &As[(m0 + i * 16) * AP + a_off + ks * 16], AP);
#pragma unroll
            for (int nn = 0; nn < 4; nn++) {
                wmma::fragment<wmma::matrix_b, 16, 16, 16, __nv_bfloat16, wmma::col_major> bf;
                wmma::load_matrix_sync(bf, &Bc[(n0 + nn * 16) * BP + ks * 16], BP);
                wmma::mma_sync(acc[0][nn], af[0], bf, acc[0][nn]);
                wmma::mma_sync(acc[1][nn], af[1], bf, acc[1][nn]);
            }
        }
    }

#pragma unroll
    for (int i = 0; i < 2; i++)
#pragma unroll
        for (int nn = 0; nn < 4; nn++)
            wmma::store_matrix_sync(
                xp + ((size_t)b * TT + m0 + i * 16) * GG + jt * 128 + n0 + nn * 16,
                acc[i][nn], GG, wmma::mem_row_major);
}

// ---------------------------------------------------------------------------
// Recurrent LSTM (best-known config, unchanged): 256 threads, 2 gate
// columns per thread. k<88 weights in smem, k>=88 in registers.
// ---------------------------------------------------------------------------
__global__ __launch_bounds__(256, 1)
void lstm_kernel(const float* __restrict__ xp,
                 const float* __restrict__ h0,
                 const float* __restrict__ c0,
                 float* __restrict__ out_enc) {
    extern __shared__ char smem_raw[];
    float4* ws  = (float4*)smem_raw;                     // [SM_K4][GG]
    float*  s_h = (float*)(smem_raw + SM_K4 * GG * 16);  // [BM][HH]
    float*  s_c = s_h + BM * HH;                         // [BM][HH]
    float*  s_g = s_c + BM * HH;                         // [BM][GG]

    int tid = threadIdx.x;
    int b0 = blockIdx.x * BM;
    int j0 = tid, j1 = tid + 256;

    for (int i = tid; i < SM_K4 * GG; i += 256) ws[i] = g_whh4[i];

    ulonglong2 wt0[32 - SM_K4], wt1[32 - SM_K4];
#pragma unroll
    for (int q = 0; q < 32 - SM_K4; q++) {
        wt0[q] = *(const ulonglong2*)&g_whh4[(SM_K4 + q) * GG + j0];
        wt1[q] = *(const ulonglong2*)&g_whh4[(SM_K4 + q) * GG + j1];
    }

    for (int i = tid; i < BM * HH; i += 256) {
        int r = i >> 7, k = i & (HH - 1);
        int b = b0 + r;
        float hv = 0.f, cv = 0.f;
        if (b < BB) { hv = h0[(size_t)b * HH + k]; cv = c0[(size_t)b * HH + k]; }
        s_h[i] = hv; s_c[i] = cv;
    }
    float bias0 = g_bias[j0], bias1 = g_bias[j1];
    __syncthreads();

    const float* xrow[BM];
#pragma unroll
    for (int r = 0; r < BM; r++) {
        int b = b0 + r; if (b > BB - 1) b = BB - 1;
        xrow[r] = xp + (size_t)b * TT * GG;
    }

    const float4* wsj0 = ws + j0;
    const float4* wsj1 = ws + j1;
    const int lin = tid * 4;
    const int er = lin >> 7, ek = lin & (HH - 1);
    const bool eact = lin < BM * HH;
    const bool ewr  = eact && (b0 + er < BB);

    for (int t = 0; t < TT; t++) {
        float xpv0[BM], xpv1[BM];
#pragma unroll
        for (int r = 0; r < BM; r++) {
            xpv0[r] = xrow[r][(size_t)t * GG + j0];
            xpv1[r] = xrow[r][(size_t)t * GG + j1];
        }

        ull acc0[BM], acc1[BM];
#pragma unroll
        for (int r = 0; r < BM; r++) { acc0[r] = 0ULL; acc1[r] = 0ULL; }

#pragma unroll
        for (int q = 0; q < 32 - SM_K4; q++) {
#pragma unroll
            for (int r = 0; r < BM; r++) {
                ulonglong2 hp = *(const ulonglong2*)&s_h[r * HH + (SM_K4 + q) * 4];
                fma2(acc0[r], hp.x, wt0[q].x); fma2(acc0[r], hp.y, wt0[q].y);
                fma2(acc1[r], hp.x, wt1[q].x); fma2(acc1[r], hp.y, wt1[q].y);
            }
        }
#pragma unroll
        for (int k4 = 0; k4 < SM_K4; k4++) {
            ulonglong2 w0 = *(const ulonglong2*)&wsj0[k4 * GG];
            ulonglong2 w1 = *(const ulonglong2*)&wsj1[k4 * GG];
#pragma unroll
            for (int r = 0; r < BM; r++) {
                ulonglong2 hp = *(const ulonglong2*)&s_h[r * HH + k4 * 4];
                fma2(acc0[r], hp.x, w0.x); fma2(acc0[r], hp.y, w0.y);
                fma2(acc1[r], hp.x, w1.x); fma2(acc1[r], hp.y, w1.y);
            }
        }

#pragma unroll
        for (int r = 0; r < BM; r++) {
            float2 p0 = unpack2(acc0[r]);
            float2 p1 = unpack2(acc1[r]);
            s_g[r * GG + j0] = p0.x + p0.y + bias0 + xpv0[r];
            s_g[r * GG + j1] = p1.x + p1.y + bias1 + xpv1[r];
        }
        __syncthreads();

        if (eact) {
            float4 gi = *(const float4*)&s_g[er * GG + ek];
            float4 gf = *(const float4*)&s_g[er * GG + HH + ek];
            float4 gg = *(const float4*)&s_g[er * GG + 2 * HH + ek];
            float4 go = *(const float4*)&s_g[er * GG + 3 * HH + ek];
            float4 cc = *(const float4*)&s_c[er * HH + ek];

            float gI[4] = {gi.x, gi.y, gi.z, gi.w};
            float gF[4] = {gf.x, gf.y, gf.z, gf.w};
            float gGv[4] = {gg.x, gg.y, gg.z, gg.w};
            float gO[4] = {go.x, go.y, go.z, go.w};
            float cC[4] = {cc.x, cc.y, cc.z, cc.w};
            float hn[4], cn[4];
#pragma unroll
            for (int l = 0; l < 4; l++) {
                float iv = fsig(gI[l]);
                float fv = fsig(gF[l]);
                float gv = ftanh(gGv[l]);
                float ov = fsig(gO[l]);
                cn[l] = fmaf(fv, cC[l], iv * gv);
                hn[l] = ov * ftanh(cn[l]);
            }
            *(float4*)&s_c[er * HH + ek] = make_float4(cn[0], cn[1], cn[2], cn[3]);
            *(float4*)&s_h[er * HH + ek] = make_float4(hn[0], hn[1], hn[2], hn[3]);
            if (ewr)
                *(float4*)(out_enc + ((size_t)(b0 + er) * TT + t) * HH + ek) =
                    make_float4(hn[0], hn[1], hn[2], hn[3]);
        }
        __syncthreads();
    }
}

// ---------------------------------------------------------------------------
// Launch
// ---------------------------------------------------------------------------
extern "C" void kernel_launch(void* const* d_in, const int* in_sizes, int n_in,
                              void* d_out, int out_size) {
    const float* x      = (const float*)d_in[0];
    const float* attn_w = (const float*)d_in[1];
    const float* attn_b = (const float*)d_in[2];
    const float* w_ih   = (const float*)d_in[3];
    const float* w_hh   = (const float*)d_in[4];
    const float* b_ih   = (const float*)d_in[5];
    const float* b_hh   = (const float*)d_in[6];
    const float* h0     = (const float*)d_in[7];
    const float* c0     = (const float*)d_in[8];

    float* out      = (float*)d_out;
    float* out_attn = out;
    float* out_enc  = out + (size_t)BB * TT * NN;

    float* xproj;
    cudaGetSymbolAddress((void**)&xproj, g_xproj);

    int lstm_smem = SM_K4 * GG * 16 + BM * HH * 4 * 2 + BM * GG * 4;  // 201728
    cudaFuncSetAttribute(lstm_kernel,
                         cudaFuncAttributeMaxDynamicSharedMemorySize, lstm_smem);
    cudaFuncSetAttribute(xproj_wmma_kernel,
                         cudaFuncAttributeMaxDynamicSharedMemorySize, XP_SMEM);

    setup_kernel<<<192, 256>>>(w_ih, w_hh, b_ih, b_hh);
    attn_kernel<<<BB, 256>>>(x, attn_w, attn_b, out_attn);
    xproj_wmma_kernel<<<dim3(4, BB), 256, XP_SMEM>>>(x, xproj);
    lstm_kernel<<<NBLK, 256, lstm_smem>>>(xproj, h0, c0, out_enc);
}

// round 12
// speedup vs baseline: 1.5240x; 1.0772x over previous
#include <cuda_runtime.h>
#include <cuda_bf16.h>
#include <mma.h>
#include <math.h>

using namespace nvcuda;

#define BB 1024
#define TT 128
#define NN 256
#define HH 128
#define GG 512
#define BM 7
#define NBLK 147
#define SM_K4 22        // k4 groups of w_hh^T in smem (k < 88); 10 in regs
#define AP 264          // A smem row pitch (bf16): 256 + 8 pad
#define BP 72           // B smem column pitch (bf16)

typedef unsigned long long ull;
typedef unsigned int u32;

// ---------------- scratch ----------------------------------------------------
__device__ float4 g_whh4[32 * GG];
__device__ float  g_bias[GG];
__device__ float  g_xproj[(size_t)BB * TT * GG];
__device__ __nv_bfloat16 g_wbf[GG * NN];   // [j][k] bf16(w_ih)

// ---------------- helpers ----------------------------------------------------
__device__ __forceinline__ void fma2(ull& d, ull a, ull b) {
    asm("fma.rn.f32x2 %0, %1, %2, %0;" : "+l"(d) : "l"(a), "l"(b));
}
__device__ __forceinline__ float2 unpack2(ull v) {
    float2 f; asm("mov.b64 {%0,%1}, %2;" : "=f"(f.x), "=f"(f.y) : "l"(v)); return f;
}
__device__ __forceinline__ float fsig(float x) {
    float e = __expf(-x); return __fdividef(1.0f, 1.0f + e);
}
__device__ __forceinline__ float ftanh(float x) {
    float e = __expf(2.0f * x); return 1.0f - __fdividef(2.0f, e + 1.0f);
}

// ---------------------------------------------------------------------------
// Setup
// ---------------------------------------------------------------------------
__global__ void setup_kernel(const float* __restrict__ w_ih,
                             const float* __restrict__ w_hh,
                             const float* __restrict__ b_ih,
                             const float* __restrict__ b_hh) {
    int idx = blockIdx.x * blockDim.x + threadIdx.x;
    int stride = gridDim.x * blockDim.x;
    if (idx < GG) g_bias[idx] = b_ih[idx] + b_hh[idx];
    for (int i = idx; i < 32 * GG; i += stride) {
        int k4 = i >> 9, j = i & (GG - 1);
        const float* wr = w_hh + j * HH + 4 * k4;
        g_whh4[i] = make_float4(wr[0], wr[1], wr[2], wr[3]);
    }
    for (int i = idx; i < GG * NN; i += stride)
        g_wbf[i] = __float2bfloat16_rn(w_ih[i]);
}

// ---------------------------------------------------------------------------
// Fused attention + xproj. One CTA per batch row b.
//   1) feat[n] = sum_t x[b,t,n]*wx[t] + bias; a = softmax_n(feat)
//      (recurrent additive term is per-row constant -> softmax-invariant)
//   2) broadcast-write attentions (a identical for all t)
//   3) A = bf16(a * x[b])  built ONCE (x now L2-hot from step 1)
//   4) wmma bf16 GEMM over all 4 j-tiles (N=512), K=256 in 4 chunks,
//      double-buffered B. 2 CTAs/SM.
// ---------------------------------------------------------------------------
#define SMX_A   0
#define SMX_B   (128 * AP * 2)                 // 67584
#define SMX_SA  (SMX_B + 2 * 128 * BP * 2)     // 104448
#define SMX_RED (SMX_SA + NN * 4)              // 105472
#define SMX_WX  (SMX_RED + 256 * 4)            // 106496
#define XP_SMEM (SMX_WX + TT * 4)              // 107008

__global__ __launch_bounds__(256, 2)
void fused_attn_xproj_kernel(const float* __restrict__ x,
                             const float* __restrict__ attn_w,
                             const float* __restrict__ attn_b,
                             float* __restrict__ out_attn,
                             float* __restrict__ xp) {
    extern __shared__ char smem[];
    __nv_bfloat16* As = (__nv_bfloat16*)(smem + SMX_A);   // [128][AP]
    __nv_bfloat16* Bs = (__nv_bfloat16*)(smem + SMX_B);   // [2][128][BP]
    float* s_a   = (float*)(smem + SMX_SA);
    float* s_red = (float*)(smem + SMX_RED);
    float* s_wx  = (float*)(smem + SMX_WX);

    int b = blockIdx.x;
    int tid = threadIdx.x;
    int wid = tid >> 5;
    int n = tid;
    const float* xb = x + (size_t)b * TT * NN;

    // ---- 1) feat + softmax ----
    if (tid < TT) s_wx[tid] = attn_w[2 * HH + tid];
    __syncthreads();

    float feat = attn_b[0];
#pragma unroll 8
    for (int t = 0; t < TT; t++) feat = fmaf(xb[(size_t)t * NN + n], s_wx[t], feat);

    s_red[n] = feat;
    __syncthreads();
#pragma unroll
    for (int s = 128; s > 0; s >>= 1) {
        if (n < s) s_red[n] = fmaxf(s_red[n], s_red[n + s]);
        __syncthreads();
    }
    float m = s_red[0];
    __syncthreads();
    float e = expf(feat - m);
    s_red[n] = e;
    __syncthreads();
#pragma unroll
    for (int s = 128; s > 0; s >>= 1) {
        if (n < s) s_red[n] += s_red[n + s];
        __syncthreads();
    }
    s_a[n] = e / s_red[0];
    __syncthreads();

    // ---- 2) attentions broadcast write (same a for every t) ----
    {
        float* ob = out_attn + (size_t)b * TT * NN;
#pragma unroll 4
        for (int i = tid; i < TT * NN / 4; i += 256) {
            int t = i >> 6, n4 = (i & 63) * 4;
            *(float4*)&ob[(size_t)t * NN + n4] = *(const float4*)&s_a[n4];
        }
    }

    // ---- 3) build A = bf16(a * x), once ----
#pragma unroll
    for (int it = 0; it < 16; it++) {
        int seg = tid + 256 * it;
        int t = seg >> 5;
        int k8 = (seg & 31) * 8;
        float4 x0 = *(const float4*)&xb[(size_t)t * NN + k8];
        float4 x1 = *(const float4*)&xb[(size_t)t * NN + k8 + 4];
        float4 a0 = *(const float4*)&s_a[k8];
        float4 a1 = *(const float4*)&s_a[k8 + 4];
        float v[8] = {x0.x * a0.x, x0.y * a0.y, x0.z * a0.z, x0.w * a0.w,
                      x1.x * a1.x, x1.y * a1.y, x1.z * a1.z, x1.w * a1.w};
        u32 hw[4];
#pragma unroll
        for (int p = 0; p < 4; p++) {
            __nv_bfloat162 hp = __halves2bfloat162(
                __float2bfloat16_rn(v[2 * p]), __float2bfloat16_rn(v[2 * p + 1]));
            hw[p] = *(u32*)&hp;
        }
        *(uint4*)&As[t * AP + k8] = make_uint4(hw[0], hw[1], hw[2], hw[3]);
    }

    // ---- 4) GEMM over jt = 0..3, c = 0..3 (16 B chunks, double buffered) ----
    int jseg = tid >> 3, kl8 = (tid & 7) * 8;   // B fill: 128 rows x 64 k per chunk
    uint4 rb[4];
#pragma unroll
    for (int it = 0; it < 4; it++) {
        int j = jseg + 32 * it;
        rb[it] = *(const uint4*)&g_wbf[(size_t)j * NN + kl8];   // jt=0, c=0
    }

    int m0 = (wid >> 1) * 32;
    int n0 = (wid & 1) * 64;

    __syncthreads();   // As visible

    int cc = 0;
    for (int jt = 0; jt < 4; jt++) {
        wmma::fragment<wmma::accumulator, 16, 16, 16, float> acc[2][4];
#pragma unroll
        for (int i = 0; i < 2; i++)
#pragma unroll
            for (int nn = 0; nn < 4; nn++) wmma::fill_fragment(acc[i][nn], 0.0f);

        for (int c = 0; c < 4; c++, cc++) {
            __nv_bfloat16* Bc = Bs + (cc & 1) * 128 * BP;
#pragma unroll
            for (int it = 0; it < 4; it++) {
                int j = jseg + 32 * it;
                *(uint4*)&Bc[j * BP + kl8] = rb[it];
            }
            __syncthreads();

            if (cc < 15) {
                int njt = (cc + 1) >> 2, nc = (cc + 1) & 3;
#pragma unroll
                for (int it = 0; it < 4; it++) {
                    int j = jseg + 32 * it;
                    rb[it] = *(const uint4*)
                        &g_wbf[(size_t)(njt * 128 + j) * NN + nc * 64 + kl8];
                }
            }

            int a_off = c * 64;
#pragma unroll
            for (int ks = 0; ks < 4; ks++) {
                wmma::fragment<wmma::matrix_a, 16, 16, 16, __nv_bfloat16, wmma::row_major> af[2];
#pragma unroll
                for (int i = 0; i < 2; i++)
                    wmma::load_matrix_sync(af[i], &As[(m0 + i * 16) * AP + a_off + ks * 16], AP);
#pragma unroll
                for (int nn = 0; nn < 4; nn++) {
                    wmma::fragment<wmma::matrix_b, 16, 16, 16, __nv_bfloat16, wmma::col_major> bf;
                    wmma::load_matrix_sync(bf, &Bc[(n0 + nn * 16) * BP + ks * 16], BP);
                    wmma::mma_sync(acc[0][nn], af[0], bf, acc[0][nn]);
                    wmma::mma_sync(acc[1][nn], af[1], bf, acc[1][nn]);
                }
            }
        }

#pragma unroll
        for (int i = 0; i < 2; i++)
#pragma unroll
            for (int nn = 0; nn < 4; nn++)
                wmma::store_matrix_sync(
                    xp + ((size_t)b * TT + m0 + i * 16) * GG + jt * 128 + n0 + nn * 16,
                    acc[i][nn], GG, wmma::mem_row_major);
    }
}

// ---------------------------------------------------------------------------
// Recurrent LSTM (best-known config, unchanged): 256 threads, 2 gate
// columns per thread. k<88 weights in smem, k>=88 in registers.
// ---------------------------------------------------------------------------
__global__ __launch_bounds__(256, 1)
void lstm_kernel(const float* __restrict__ xp,
                 const float* __restrict__ h0,
                 const float* __restrict__ c0,
                 float* __restrict__ out_enc) {
    extern __shared__ char smem_raw[];
    float4* ws  = (float4*)smem_raw;                     // [SM_K4][GG]
    float*  s_h = (float*)(smem_raw + SM_K4 * GG * 16);  // [BM][HH]
    float*  s_c = s_h + BM * HH;                         // [BM][HH]
    float*  s_g = s_c + BM * HH;                         // [BM][GG]

    int tid = threadIdx.x;
    int b0 = blockIdx.x * BM;
    int j0 = tid, j1 = tid + 256;

    for (int i = tid; i < SM_K4 * GG; i += 256) ws[i] = g_whh4[i];

    ulonglong2 wt0[32 - SM_K4], wt1[32 - SM_K4];
#pragma unroll
    for (int q = 0; q < 32 - SM_K4; q++) {
        wt0[q] = *(const ulonglong2*)&g_whh4[(SM_K4 + q) * GG + j0];
        wt1[q] = *(const ulonglong2*)&g_whh4[(SM_K4 + q) * GG + j1];
    }

    for (int i = tid; i < BM * HH; i += 256) {
        int r = i >> 7, k = i & (HH - 1);
        int b = b0 + r;
        float hv = 0.f, cv = 0.f;
        if (b < BB) { hv = h0[(size_t)b * HH + k]; cv = c0[(size_t)b * HH + k]; }
        s_h[i] = hv; s_c[i] = cv;
    }
    float bias0 = g_bias[j0], bias1 = g_bias[j1];
    __syncthreads();

    const float* xrow[BM];
#pragma unroll
    for (int r = 0; r < BM; r++) {
        int b = b0 + r; if (b > BB - 1) b = BB - 1;
        xrow[r] = xp + (size_t)b * TT * GG;
    }

    const float4* wsj0 = ws + j0;
    const float4* wsj1 = ws + j1;
    const int lin = tid * 4;
    const int er = lin >> 7, ek = lin & (HH - 1);
    const bool eact = lin < BM * HH;
    const bool ewr  = eact && (b0 + er < BB);

    for (int t = 0; t < TT; t++) {
        float xpv0[BM], xpv1[BM];
#pragma unroll
        for (int r = 0; r < BM; r++) {
            xpv0[r] = xrow[r][(size_t)t * GG + j0];
            xpv1[r] = xrow[r][(size_t)t * GG + j1];
        }

        ull acc0[BM], acc1[BM];
#pragma unroll
        for (int r = 0; r < BM; r++) { acc0[r] = 0ULL; acc1[r] = 0ULL; }

#pragma unroll
        for (int q = 0; q < 32 - SM_K4; q++) {
#pragma unroll
            for (int r = 0; r < BM; r++) {
                ulonglong2 hp = *(const ulonglong2*)&s_h[r * HH + (SM_K4 + q) * 4];
                fma2(acc0[r], hp.x, wt0[q].x); fma2(acc0[r], hp.y, wt0[q].y);
                fma2(acc1[r], hp.x, wt1[q].x); fma2(acc1[r], hp.y, wt1[q].y);
            }
        }
#pragma unroll
        for (int k4 = 0; k4 < SM_K4; k4++) {
            ulonglong2 w0 = *(const ulonglong2*)&wsj0[k4 * GG];
            ulonglong2 w1 = *(const ulonglong2*)&wsj1[k4 * GG];
#pragma unroll
            for (int r = 0; r < BM; r++) {
                ulonglong2 hp = *(const ulonglong2*)&s_h[r * HH + k4 * 4];
                fma2(acc0[r], hp.x, w0.x); fma2(acc0[r], hp.y, w0.y);
                fma2(acc1[r], hp.x, w1.x); fma2(acc1[r], hp.y, w1.y);
            }
        }

#pragma unroll
        for (int r = 0; r < BM; r++) {
            float2 p0 = unpack2(acc0[r]);
            float2 p1 = unpack2(acc1[r]);
            s_g[r * GG + j0] = p0.x + p0.y + bias0 + xpv0[r];
            s_g[r * GG + j1] = p1.x + p1.y + bias1 + xpv1[r];
        }
        __syncthreads();

        if (eact) {
            float4 gi = *(const float4*)&s_g[er * GG + ek];
            float4 gf = *(const float4*)&s_g[er * GG + HH + ek];
            float4 gg = *(const float4*)&s_g[er * GG + 2 * HH + ek];
            float4 go = *(const float4*)&s_g[er * GG + 3 * HH + ek];
            float4 cc = *(const float4*)&s_c[er * HH + ek];

            float gI[4] = {gi.x, gi.y, gi.z, gi.w};
            float gF[4] = {gf.x, gf.y, gf.z, gf.w};
            float gGv[4] = {gg.x, gg.y, gg.z, gg.w};
            float gO[4] = {go.x, go.y, go.z, go.w};
            float cC[4] = {cc.x, cc.y, cc.z, cc.w};
            float hn[4], cn[4];
#pragma unroll
            for (int l = 0; l < 4; l++) {
                float iv = fsig(gI[l]);
                float fv = fsig(gF[l]);
                float gv = ftanh(gGv[l]);
                float ov = fsig(gO[l]);
                cn[l] = fmaf(fv, cC[l], iv * gv);
                hn[l] = ov * ftanh(cn[l]);
            }
            *(float4*)&s_c[er * HH + ek] = make_float4(cn[0], cn[1], cn[2], cn[3]);
            *(float4*)&s_h[er * HH + ek] = make_float4(hn[0], hn[1], hn[2], hn[3]);
            if (ewr)
                *(float4*)(out_enc + ((size_t)(b0 + er) * TT + t) * HH + ek) =
                    make_float4(hn[0], hn[1], hn[2], hn[3]);
        }
        __syncthreads();
    }
}

// ---------------------------------------------------------------------------
// Launch
// ---------------------------------------------------------------------------
extern "C" void kernel_launch(void* const* d_in, const int* in_sizes, int n_in,
                              void* d_out, int out_size) {
    const float* x      = (const float*)d_in[0];
    const float* attn_w = (const float*)d_in[1];
    const float* attn_b = (const float*)d_in[2];
    const float* w_ih   = (const float*)d_in[3];
    const float* w_hh   = (const float*)d_in[4];
    const float* b_ih   = (const float*)d_in[5];
    const float* b_hh   = (const float*)d_in[6];
    const float* h0     = (const float*)d_in[7];
    const float* c0     = (const float*)d_in[8];

    float* out      = (float*)d_out;
    float* out_attn = out;
    float* out_enc  = out + (size_t)BB * TT * NN;

    float* xproj;
    cudaGetSymbolAddress((void**)&xproj, g_xproj);

    int lstm_smem = SM_K4 * GG * 16 + BM * HH * 4 * 2 + BM * GG * 4;  // 201728
    cudaFuncSetAttribute(lstm_kernel,
                         cudaFuncAttributeMaxDynamicSharedMemorySize, lstm_smem);
    cudaFuncSetAttribute(fused_attn_xproj_kernel,
                         cudaFuncAttributeMaxDynamicSharedMemorySize, XP_SMEM);

    setup_kernel<<<192, 256>>>(w_ih, w_hh, b_ih, b_hh);
    fused_attn_xproj_kernel<<<BB, 256, XP_SMEM>>>(x, attn_w, attn_b, out_attn, xproj);
    lstm_kernel<<<NBLK, 256, lstm_smem>>>(xproj, h0, c0, out_enc);
}

// round 13
// speedup vs baseline: 2.2046x; 1.4466x over previous
#include <cuda_runtime.h>
#include <cuda_bf16.h>
#include <mma.h>
#include <math.h>

using namespace nvcuda;

#define BB 1024
#define TT 128
#define NN 256
#define HH 128
#define GG 512
#define BM 7
#define NBLK 147
#define AP 264          // xproj A pitch (bf16)
#define BP 72           // xproj B pitch (bf16)
#define BPL 136         // lstm B (w_hh) smem pitch (bf16 elems)
#define APL 136         // lstm A (h hi/lo) smem pitch (bf16 elems)
#define ACCP 520        // lstm acc smem pitch (fp32 elems)

typedef unsigned long long ull;
typedef unsigned int u32;

// ---------------- scratch ----------------------------------------------------
__device__ float  g_bias[GG];
__device__ float  g_xproj[(size_t)BB * TT * GG];
__device__ __nv_bfloat16 g_wbf[GG * NN];    // [j][k] bf16(w_ih)
__device__ __nv_bfloat16 g_whhbf[GG * HH];  // [j][k] bf16(w_hh)

// ---------------- helpers ----------------------------------------------------
__device__ __forceinline__ float fsig(float x) {
    float e = __expf(-x); return __fdividef(1.0f, 1.0f + e);
}
__device__ __forceinline__ float ftanh(float x) {
    float e = __expf(2.0f * x); return 1.0f - __fdividef(2.0f, e + 1.0f);
}
// pack 4 floats to 4 bf16 (hi) in one ull
__device__ __forceinline__ ull pack_bf4(float a, float b, float c, float d) {
    __nv_bfloat162 p01 = __halves2bfloat162(__float2bfloat16_rn(a), __float2bfloat16_rn(b));
    __nv_bfloat162 p23 = __halves2bfloat162(__float2bfloat16_rn(c), __float2bfloat16_rn(d));
    return (ull)(*(u32*)&p01) | ((ull)(*(u32*)&p23) << 32);
}

// ---------------------------------------------------------------------------
// Setup
// ---------------------------------------------------------------------------
__global__ void setup_kernel(const float* __restrict__ w_ih,
                             const float* __restrict__ w_hh,
                             const float* __restrict__ b_ih,
                             const float* __restrict__ b_hh) {
    int idx = blockIdx.x * blockDim.x + threadIdx.x;
    int stride = gridDim.x * blockDim.x;
    if (idx < GG) g_bias[idx] = b_ih[idx] + b_hh[idx];
    for (int i = idx; i < GG * NN; i += stride)
        g_wbf[i] = __float2bfloat16_rn(w_ih[i]);
    for (int i = idx; i < GG * HH; i += stride)
        g_whhbf[i] = __float2bfloat16_rn(w_hh[i]);
}

// ---------------------------------------------------------------------------
// Fused attention + xproj (unchanged from R11, ~190us). One CTA per b.
// ---------------------------------------------------------------------------
#define SMX_A   0
#define SMX_B   (128 * AP * 2)
#define SMX_SA  (SMX_B + 2 * 128 * BP * 2)
#define SMX_RED (SMX_SA + NN * 4)
#define SMX_WX  (SMX_RED + 256 * 4)
#define XP_SMEM (SMX_WX + TT * 4)

__global__ __launch_bounds__(256, 2)
void fused_attn_xproj_kernel(const float* __restrict__ x,
                             const float* __restrict__ attn_w,
                             const float* __restrict__ attn_b,
                             float* __restrict__ out_attn,
                             float* __restrict__ xp) {
    extern __shared__ char smem[];
    __nv_bfloat16* As = (__nv_bfloat16*)(smem + SMX_A);
    __nv_bfloat16* Bs = (__nv_bfloat16*)(smem + SMX_B);
    float* s_a   = (float*)(smem + SMX_SA);
    float* s_red = (float*)(smem + SMX_RED);
    float* s_wx  = (float*)(smem + SMX_WX);

    int b = blockIdx.x;
    int tid = threadIdx.x;
    int wid = tid >> 5;
    int n = tid;
    const float* xb = x + (size_t)b * TT * NN;

    if (tid < TT) s_wx[tid] = attn_w[2 * HH + tid];
    __syncthreads();

    float feat = attn_b[0];
#pragma unroll 8
    for (int t = 0; t < TT; t++) feat = fmaf(xb[(size_t)t * NN + n], s_wx[t], feat);

    s_red[n] = feat;
    __syncthreads();
#pragma unroll
    for (int s = 128; s > 0; s >>= 1) {
        if (n < s) s_red[n] = fmaxf(s_red[n], s_red[n + s]);
        __syncthreads();
    }
    float m = s_red[0];
    __syncthreads();
    float e = expf(feat - m);
    s_red[n] = e;
    __syncthreads();
#pragma unroll
    for (int s = 128; s > 0; s >>= 1) {
        if (n < s) s_red[n] += s_red[n + s];
        __syncthreads();
    }
    s_a[n] = e / s_red[0];
    __syncthreads();

    {
        float* ob = out_attn + (size_t)b * TT * NN;
#pragma unroll 4
        for (int i = tid; i < TT * NN / 4; i += 256) {
            int t = i >> 6, n4 = (i & 63) * 4;
            *(float4*)&ob[(size_t)t * NN + n4] = *(const float4*)&s_a[n4];
        }
    }

#pragma unroll
    for (int it = 0; it < 16; it++) {
        int seg = tid + 256 * it;
        int t = seg >> 5;
        int k8 = (seg & 31) * 8;
        float4 x0 = *(const float4*)&xb[(size_t)t * NN + k8];
        float4 x1 = *(const float4*)&xb[(size_t)t * NN + k8 + 4];
        float4 a0 = *(const float4*)&s_a[k8];
        float4 a1 = *(const float4*)&s_a[k8 + 4];
        float v[8] = {x0.x * a0.x, x0.y * a0.y, x0.z * a0.z, x0.w * a0.w,
                      x1.x * a1.x, x1.y * a1.y, x1.z * a1.z, x1.w * a1.w};
        u32 hw[4];
#pragma unroll
        for (int p = 0; p < 4; p++) {
            __nv_bfloat162 hp = __halves2bfloat162(
                __float2bfloat16_rn(v[2 * p]), __float2bfloat16_rn(v[2 * p + 1]));
            hw[p] = *(u32*)&hp;
        }
        *(uint4*)&As[t * AP + k8] = make_uint4(hw[0], hw[1], hw[2], hw[3]);
    }

    int jseg = tid >> 3, kl8 = (tid & 7) * 8;
    uint4 rb[4];
#pragma unroll
    for (int it = 0; it < 4; it++) {
        int j = jseg + 32 * it;
        rb[it] = *(const uint4*)&g_wbf[(size_t)j * NN + kl8];
    }

    int m0 = (wid >> 1) * 32;
    int n0 = (wid & 1) * 64;

    __syncthreads();

    int cc = 0;
    for (int jt = 0; jt < 4; jt++) {
        wmma::fragment<wmma::accumulator, 16, 16, 16, float> acc[2][4];
#pragma unroll
        for (int i = 0; i < 2; i++)
#pragma unroll
            for (int nn = 0; nn < 4; nn++) wmma::fill_fragment(acc[i][nn], 0.0f);

        for (int c = 0; c < 4; c++, cc++) {
            __nv_bfloat16* Bc = Bs + (cc & 1) * 128 * BP;
#pragma unroll
            for (int it = 0; it < 4; it++) {
                int j = jseg + 32 * it;
                *(uint4*)&Bc[j * BP + kl8] = rb[it];
            }
            __syncthreads();

            if (cc < 15) {
                int njt = (cc + 1) >> 2, nc = (cc + 1) & 3;
#pragma unroll
                for (int it = 0; it < 4; it++) {
                    int j = jseg + 32 * it;
                    rb[it] = *(const uint4*)
                        &g_wbf[(size_t)(njt * 128 + j) * NN + nc * 64 + kl8];
                }
            }

            int a_off = c * 64;
#pragma unroll
            for (int ks = 0; ks < 4; ks++) {
                wmma::fragment<wmma::matrix_a, 16, 16, 16, __nv_bfloat16, wmma::row_major> af[2];
#pragma unroll
                for (int i = 0; i < 2; i++)
                    wmma::load_matrix_sync(af[i], &As[(m0 + i * 16) * AP + a_off + ks * 16], AP);
#pragma unroll
                for (int nn = 0; nn < 4; nn++) {
                    wmma::fragment<wmma::matrix_b, 16, 16, 16, __nv_bfloat16, wmma::col_major> bf;
                    wmma::load_matrix_sync(bf, &Bc[(n0 + nn * 16) * BP + ks * 16], BP);
                    wmma::mma_sync(acc[0][nn], af[0], bf, acc[0][nn]);
                    wmma::mma_sync(acc[1][nn], af[1], bf, acc[1][nn]);
                }
            }
        }

#pragma unroll
        for (int i = 0; i < 2; i++)
#pragma unroll
            for (int nn = 0; nn < 4; nn++)
                wmma::store_matrix_sync(
                    xp + ((size_t)b * TT + m0 + i * 16) * GG + jt * 128 + n0 + nn * 16,
                    acc[i][nn], GG, wmma::mem_row_major);
    }
}

// ---------------------------------------------------------------------------
// Recurrent LSTM via wmma with hi/lo row packing.
// A tile [16][128] bf16: rows 0-6 = bf16_hi(h[r]), rows 8-14 = residual lo,
// rows 7/15 zero. One MMA pass -> gates[r][j] = acc[r][j] + acc[r+8][j].
// B = bf16(w_hh) [512j][128k] in smem for all 128 steps. c-state in regs.
// 8 warps: warp w covers j = w*64 .. w*64+63 (4 n-tiles).
// ---------------------------------------------------------------------------
#define SMB_L   0                            // 512*136*2 = 139264
#define SMA_L   139264                       // 16*136*2  = 4352
#define SMACC_L 143616                       // 16*520*4  = 33280
#define LSTM_SMEM 176896

__global__ __launch_bounds__(256, 1)
void lstm_wmma_kernel(const float* __restrict__ xp,
                      const float* __restrict__ h0,
                      const float* __restrict__ c0,
                      float* __restrict__ out_enc) {
    extern __shared__ char smem[];
    __nv_bfloat16* Bs    = (__nv_bfloat16*)(smem + SMB_L);   // [512][BPL]
    __nv_bfloat16* As    = (__nv_bfloat16*)(smem + SMA_L);   // [16][APL]
    float*         s_acc = (float*)(smem + SMACC_L);         // [16][ACCP]

    int tid = threadIdx.x;
    int wid = tid >> 5;
    int b0 = blockIdx.x * BM;

    // ---- load w_hh bf16 into smem (once) ----
    for (int i = tid; i < GG * HH / 8; i += 256) {
        int j = i >> 4, k8 = (i & 15) * 8;
        *(uint4*)&Bs[j * BPL + k8] = *(const uint4*)&g_whhbf[j * HH + k8];
    }

    // ---- epilogue ownership: thread (tid<224) owns cells (er, ek..ek+3) ----
    const int lin = tid * 4;
    const int er = lin >> 7, ek = lin & 127;
    const bool eact = tid < 224;
    const bool ewr  = eact && (b0 + er < BB);

    float c_reg[4] = {0.f, 0.f, 0.f, 0.f};
    float4 bias_g[4];

    if (eact) {
        // init c in regs, h -> A hi/lo
        float4 hv = make_float4(0.f, 0.f, 0.f, 0.f);
        if (ewr) {
            hv = *(const float4*)&h0[(size_t)(b0 + er) * HH + ek];
            float4 cv = *(const float4*)&c0[(size_t)(b0 + er) * HH + ek];
            c_reg[0] = cv.x; c_reg[1] = cv.y; c_reg[2] = cv.z; c_reg[3] = cv.w;
        }
        ull hi = pack_bf4(hv.x, hv.y, hv.z, hv.w);
        float4 hr;
        hr.x = hv.x - __bfloat162float(__float2bfloat16_rn(hv.x));
        hr.y = hv.y - __bfloat162float(__float2bfloat16_rn(hv.y));
        hr.z = hv.z - __bfloat162float(__float2bfloat16_rn(hv.z));
        hr.w = hv.w - __bfloat162float(__float2bfloat16_rn(hv.w));
        ull lo = pack_bf4(hr.x, hr.y, hr.z, hr.w);
        *(ull*)&As[er * APL + ek]       = hi;
        *(ull*)&As[(er + 8) * APL + ek] = lo;
#pragma unroll
        for (int g = 0; g < 4; g++)
            bias_g[g] = *(const float4*)&g_bias[g * 128 + ek];
    } else {
        // zero A rows 7 and 15 (incl. pad cols)
        int q = tid - 224;                       // 0..31
        for (int i = q; i < 2 * (APL / 4); i += 32) {
            int row = (i < APL / 4) ? 7 : 15;
            int col = (i % (APL / 4)) * 4;
            *(ull*)&As[row * APL + col] = 0ULL;
        }
    }

    // xp row pointer (clamped for pad rows; loads harmless)
    int bclamp = b0 + er; if (bclamp > BB - 1) bclamp = BB - 1;
    const float* xrow_e = xp + (size_t)bclamp * TT * GG;

    const int n0 = wid * 64;
    __syncthreads();

    for (int t = 0; t < TT; t++) {
        // prefetch xproj for this step (consumed after MMA)
        float4 xpv[4];
        if (eact) {
#pragma unroll
            for (int g = 0; g < 4; g++)
                xpv[g] = *(const float4*)&xrow_e[(size_t)t * GG + g * 128 + ek];
        }

        // ---- MMA: acc[16][j-slice] = A[16][128] @ B[128][j-slice] ----
        wmma::fragment<wmma::matrix_a, 16, 16, 16, __nv_bfloat16, wmma::row_major> af[8];
#pragma unroll
        for (int ks = 0; ks < 8; ks++)
            wmma::load_matrix_sync(af[ks], &As[ks * 16], APL);

#pragma unroll
        for (int nt = 0; nt < 4; nt++) {
            wmma::fragment<wmma::accumulator, 16, 16, 16, float> acc;
            wmma::fill_fragment(acc, 0.0f);
#pragma unroll
            for (int ks = 0; ks < 8; ks++) {
                wmma::fragment<wmma::matrix_b, 16, 16, 16, __nv_bfloat16, wmma::col_major> bf;
                wmma::load_matrix_sync(bf, &Bs[(n0 + nt * 16) * BPL + ks * 16], BPL);
                wmma::mma_sync(acc, af[ks], bf, acc);
            }
            wmma::store_matrix_sync(&s_acc[n0 + nt * 16], acc, ACCP, wmma::mem_row_major);
        }
        __syncthreads();

        // ---- epilogue: gates = acc_hi + acc_lo + bias + xproj ----
        if (eact) {
            float gate[4][4];
#pragma unroll
            for (int g = 0; g < 4; g++) {
                float4 ahi = *(const float4*)&s_acc[er * ACCP + g * 128 + ek];
                float4 alo = *(const float4*)&s_acc[(er + 8) * ACCP + g * 128 + ek];
                float4 bg = bias_g[g];
                float4 xv = xpv[g];
                gate[g][0] = ahi.x + alo.x + bg.x + xv.x;
                gate[g][1] = ahi.y + alo.y + bg.y + xv.y;
                gate[g][2] = ahi.z + alo.z + bg.z + xv.z;
                gate[g][3] = ahi.w + alo.w + bg.w + xv.w;
            }
            float hn[4];
#pragma unroll
            for (int l = 0; l < 4; l++) {
                float iv = fsig(gate[0][l]);
                float fv = fsig(gate[1][l]);
                float gv = ftanh(gate[2][l]);
                float ov = fsig(gate[3][l]);
                c_reg[l] = fmaf(fv, c_reg[l], iv * gv);
                hn[l] = ov * ftanh(c_reg[l]);
            }
            // write h hi/lo into A for next step
            ull hi = pack_bf4(hn[0], hn[1], hn[2], hn[3]);
            float r0 = hn[0] - __bfloat162float(__float2bfloat16_rn(hn[0]));
            float r1 = hn[1] - __bfloat162float(__float2bfloat16_rn(hn[1]));
            float r2 = hn[2] - __bfloat162float(__float2bfloat16_rn(hn[2]));
            float r3 = hn[3] - __bfloat162float(__float2bfloat16_rn(hn[3]));
            ull lo = pack_bf4(r0, r1, r2, r3);
            *(ull*)&As[er * APL + ek]       = hi;
            *(ull*)&As[(er + 8) * APL + ek] = lo;
            if (ewr)
                *(float4*)(out_enc + ((size_t)(b0 + er) * TT + t) * HH + ek) =
                    make_float4(hn[0], hn[1], hn[2], hn[3]);
        }
        __syncthreads();
    }
}

// ---------------------------------------------------------------------------
// Launch
// ---------------------------------------------------------------------------
extern "C" void kernel_launch(void* const* d_in, const int* in_sizes, int n_in,
                              void* d_out, int out_size) {
    const float* x      = (const float*)d_in[0];
    const float* attn_w = (const float*)d_in[1];
    const float* attn_b = (const float*)d_in[2];
    const float* w_ih   = (const float*)d_in[3];
    const float* w_hh   = (const float*)d_in[4];
    const float* b_ih   = (const float*)d_in[5];
    const float* b_hh   = (const float*)d_in[6];
    const float* h0     = (const float*)d_in[7];
    const float* c0     = (const float*)d_in[8];

    float* out      = (float*)d_out;
    float* out_attn = out;
    float* out_enc  = out + (size_t)BB * TT * NN;

    float* xproj;
    cudaGetSymbolAddress((void**)&xproj, g_xproj);

    cudaFuncSetAttribute(lstm_wmma_kernel,
                         cudaFuncAttributeMaxDynamicSharedMemorySize, LSTM_SMEM);
    cudaFuncSetAttribute(fused_attn_xproj_kernel,
                         cudaFuncAttributeMaxDynamicSharedMemorySize, XP_SMEM);

    setup_kernel<<<192, 256>>>(w_ih, w_hh, b_ih, b_hh);
    fused_attn_xproj_kernel<<<BB, 256, XP_SMEM>>>(x, attn_w, attn_b, out_attn, xproj);
    lstm_wmma_kernel<<<NBLK, 256, LSTM_SMEM>>>(xproj, h0, c0, out_enc);
}

// round 14
// speedup vs baseline: 2.3552x; 1.0683x over previous
#include <cuda_runtime.h>
#include <cuda_bf16.h>
#include <mma.h>
#include <math.h>

using namespace nvcuda;

#define BB 1024
#define TT 128
#define NN 256
#define HH 128
#define GG 512
#define BM 7
#define NBLK 147
#define AP 264          // xproj A pitch (bf16)
#define BP 72           // xproj B pitch (bf16)
#define APL 136         // lstm A pitch (bf16)
#define ACW 68          // lstm per-warp acc pitch (fp32)

typedef unsigned long long ull;
typedef unsigned int u32;

// ---------------- scratch ----------------------------------------------------
__device__ float  g_bias[GG];
__device__ float  g_xproj[(size_t)BB * TT * GG];
__device__ __nv_bfloat16 g_wbf[GG * NN];    // [j][k] bf16(w_ih)
__device__ __nv_bfloat16 g_whhbf[GG * HH];  // [j][k] bf16(w_hh)

// ---------------- helpers ----------------------------------------------------
__device__ __forceinline__ float fsig(float x) {
    float e = __expf(-x); return __fdividef(1.0f, 1.0f + e);
}
__device__ __forceinline__ float ftanh(float x) {
    float e = __expf(2.0f * x); return 1.0f - __fdividef(2.0f, e + 1.0f);
}
__device__ __forceinline__ ull pack_bf4(float a, float b, float c, float d) {
    __nv_bfloat162 p01 = __halves2bfloat162(__float2bfloat16_rn(a), __float2bfloat16_rn(b));
    __nv_bfloat162 p23 = __halves2bfloat162(__float2bfloat16_rn(c), __float2bfloat16_rn(d));
    return (ull)(*(u32*)&p01) | ((ull)(*(u32*)&p23) << 32);
}

// ---------------------------------------------------------------------------
// Setup
// ---------------------------------------------------------------------------
__global__ void setup_kernel(const float* __restrict__ w_ih,
                             const float* __restrict__ w_hh,
                             const float* __restrict__ b_ih,
                             const float* __restrict__ b_hh) {
    int idx = blockIdx.x * blockDim.x + threadIdx.x;
    int stride = gridDim.x * blockDim.x;
    if (idx < GG) g_bias[idx] = b_ih[idx] + b_hh[idx];
    for (int i = idx; i < GG * NN; i += stride)
        g_wbf[i] = __float2bfloat16_rn(w_ih[i]);
    for (int i = idx; i < GG * HH; i += stride)
        g_whhbf[i] = __float2bfloat16_rn(w_hh[i]);
}

// ---------------------------------------------------------------------------
// Fused attention + xproj (unchanged; ~190us). One CTA per b.
// ---------------------------------------------------------------------------
#define SMX_A   0
#define SMX_B   (128 * AP * 2)
#define SMX_SA  (SMX_B + 2 * 128 * BP * 2)
#define SMX_RED (SMX_SA + NN * 4)
#define SMX_WX  (SMX_RED + 256 * 4)
#define XP_SMEM (SMX_WX + TT * 4)

__global__ __launch_bounds__(256, 2)
void fused_attn_xproj_kernel(const float* __restrict__ x,
                             const float* __restrict__ attn_w,
                             const float* __restrict__ attn_b,
                             float* __restrict__ out_attn,
                             float* __restrict__ xp) {
    extern __shared__ char smem[];
    __nv_bfloat16* As = (__nv_bfloat16*)(smem + SMX_A);
    __nv_bfloat16* Bs = (__nv_bfloat16*)(smem + SMX_B);
    float* s_a   = (float*)(smem + SMX_SA);
    float* s_red = (float*)(smem + SMX_RED);
    float* s_wx  = (float*)(smem + SMX_WX);

    int b = blockIdx.x;
    int tid = threadIdx.x;
    int wid = tid >> 5;
    int n = tid;
    const float* xb = x + (size_t)b * TT * NN;

    if (tid < TT) s_wx[tid] = attn_w[2 * HH + tid];
    __syncthreads();

    float feat = attn_b[0];
#pragma unroll 8
    for (int t = 0; t < TT; t++) feat = fmaf(xb[(size_t)t * NN + n], s_wx[t], feat);

    s_red[n] = feat;
    __syncthreads();
#pragma unroll
    for (int s = 128; s > 0; s >>= 1) {
        if (n < s) s_red[n] = fmaxf(s_red[n], s_red[n + s]);
        __syncthreads();
    }
    float m = s_red[0];
    __syncthreads();
    float e = expf(feat - m);
    s_red[n] = e;
    __syncthreads();
#pragma unroll
    for (int s = 128; s > 0; s >>= 1) {
        if (n < s) s_red[n] += s_red[n + s];
        __syncthreads();
    }
    s_a[n] = e / s_red[0];
    __syncthreads();

    {
        float* ob = out_attn + (size_t)b * TT * NN;
#pragma unroll 4
        for (int i = tid; i < TT * NN / 4; i += 256) {
            int t = i >> 6, n4 = (i & 63) * 4;
            *(float4*)&ob[(size_t)t * NN + n4] = *(const float4*)&s_a[n4];
        }
    }

#pragma unroll
    for (int it = 0; it < 16; it++) {
        int seg = tid + 256 * it;
        int t = seg >> 5;
        int k8 = (seg & 31) * 8;
        float4 x0 = *(const float4*)&xb[(size_t)t * NN + k8];
        float4 x1 = *(const float4*)&xb[(size_t)t * NN + k8 + 4];
        float4 a0 = *(const float4*)&s_a[k8];
        float4 a1 = *(const float4*)&s_a[k8 + 4];
        float v[8] = {x0.x * a0.x, x0.y * a0.y, x0.z * a0.z, x0.w * a0.w,
                      x1.x * a1.x, x1.y * a1.y, x1.z * a1.z, x1.w * a1.w};
        u32 hw[4];
#pragma unroll
        for (int p = 0; p < 4; p++) {
            __nv_bfloat162 hp = __halves2bfloat162(
                __float2bfloat16_rn(v[2 * p]), __float2bfloat16_rn(v[2 * p + 1]));
            hw[p] = *(u32*)&hp;
        }
        *(uint4*)&As[t * AP + k8] = make_uint4(hw[0], hw[1], hw[2], hw[3]);
    }

    int jseg = tid >> 3, kl8 = (tid & 7) * 8;
    uint4 rb[4];
#pragma unroll
    for (int it = 0; it < 4; it++) {
        int j = jseg + 32 * it;
        rb[it] = *(const uint4*)&g_wbf[(size_t)j * NN + kl8];
    }

    int m0 = (wid >> 1) * 32;
    int n0 = (wid & 1) * 64;

    __syncthreads();

    int cc = 0;
    for (int jt = 0; jt < 4; jt++) {
        wmma::fragment<wmma::accumulator, 16, 16, 16, float> acc[2][4];
#pragma unroll
        for (int i = 0; i < 2; i++)
#pragma unroll
            for (int nn = 0; nn < 4; nn++) wmma::fill_fragment(acc[i][nn], 0.0f);

        for (int c = 0; c < 4; c++, cc++) {
            __nv_bfloat16* Bc = Bs + (cc & 1) * 128 * BP;
#pragma unroll
            for (int it = 0; it < 4; it++) {
                int j = jseg + 32 * it;
                *(uint4*)&Bc[j * BP + kl8] = rb[it];
            }
            __syncthreads();

            if (cc < 15) {
                int njt = (cc + 1) >> 2, nc = (cc + 1) & 3;
#pragma unroll
                for (int it = 0; it < 4; it++) {
                    int j = jseg + 32 * it;
                    rb[it] = *(const uint4*)
                        &g_wbf[(size_t)(njt * 128 + j) * NN + nc * 64 + kl8];
                }
            }

            int a_off = c * 64;
#pragma unroll
            for (int ks = 0; ks < 4; ks++) {
                wmma::fragment<wmma::matrix_a, 16, 16, 16, __nv_bfloat16, wmma::row_major> af[2];
#pragma unroll
                for (int i = 0; i < 2; i++)
                    wmma::load_matrix_sync(af[i], &As[(m0 + i * 16) * AP + a_off + ks * 16], AP);
#pragma unroll
                for (int nn = 0; nn < 4; nn++) {
                    wmma::fragment<wmma::matrix_b, 16, 16, 16, __nv_bfloat16, wmma::col_major> bf;
                    wmma::load_matrix_sync(bf, &Bc[(n0 + nn * 16) * BP + ks * 16], BP);
                    wmma::mma_sync(acc[0][nn], af[0], bf, acc[0][nn]);
                    wmma::mma_sync(acc[1][nn], af[1], bf, acc[1][nn]);
                }
            }
        }

#pragma unroll
        for (int i = 0; i < 2; i++)
#pragma unroll
            for (int nn = 0; nn < 4; nn++)
                wmma::store_matrix_sync(
                    xp + ((size_t)b * TT + m0 + i * 16) * GG + jt * 128 + n0 + nn * 16,
                    acc[i][nn], GG, wmma::mem_row_major);
    }
}

// ---------------------------------------------------------------------------
// Recurrent LSTM via wmma, v2:
//  - B (w_hh bf16) fragments hoisted into REGISTERS for all 128 steps
//  - warp w owns columns {g*128 + w*16 .. +16} for all 4 gates -> epilogue is
//    warp-local (per-warp acc slab + __syncwarp)
//  - A tile (h hi/lo rows) double-buffered -> ONE __syncthreads per step
// ---------------------------------------------------------------------------
__global__ __launch_bounds__(256, 1)
void lstm_wmma_kernel(const float* __restrict__ xp,
                      const float* __restrict__ h0,
                      const float* __restrict__ c0,
                      float* __restrict__ out_enc) {
    __shared__ __nv_bfloat16 As[2][16 * APL];       // double-buffered A (h hi/lo)
    __shared__ float s_acc[8][16 * ACW];            // per-warp acc slab
    __shared__ float s_bias[GG];

    int tid = threadIdx.x;
    int wid = tid >> 5;
    int lane = tid & 31;
    int b0 = blockIdx.x * BM;

    // ---- hoist B fragments: warp w, gate g, kstep ks ----
    // tile columns j in [g*128 + w*16, +16), rows k in [ks*16, +16)
    wmma::fragment<wmma::matrix_b, 16, 16, 16, __nv_bfloat16, wmma::col_major> bf[4][8];
#pragma unroll
    for (int g = 0; g < 4; g++)
#pragma unroll
        for (int ks = 0; ks < 8; ks++)
            wmma::load_matrix_sync(bf[g][ks],
                g_whhbf + (size_t)(g * 128 + wid * 16) * HH + ks * 16, HH);

    for (int i = tid; i < GG; i += 256) s_bias[i] = g_bias[i];

    // zero A rows 7 and 15 in BOTH buffers (never rewritten)
    for (int i = tid; i < 2 * (APL / 4); i += 256) {
        int row = (i < APL / 4) ? 7 : 15;
        int col = (i % (APL / 4)) * 4;
        *(ull*)&As[0][row * APL + col] = 0ULL;
        *(ull*)&As[1][row * APL + col] = 0ULL;
    }

    // ---- epilogue ownership: warp w, lane l<28: cell (r, w*16+kq .. +3) ----
    const int er = lane >> 2;                 // 0..6
    const int kq = (lane & 3) * 4;            // 0,4,8,12
    const int kk = wid * 16 + kq;             // global k (hidden index)
    const bool eact = lane < 28;
    const bool ewr  = eact && (b0 + er < BB);

    float c_reg[4] = {0.f, 0.f, 0.f, 0.f};
    if (eact) {
        float4 hv = make_float4(0.f, 0.f, 0.f, 0.f);
        if (ewr) {
            hv = *(const float4*)&h0[(size_t)(b0 + er) * HH + kk];
            float4 cv = *(const float4*)&c0[(size_t)(b0 + er) * HH + kk];
            c_reg[0] = cv.x; c_reg[1] = cv.y; c_reg[2] = cv.z; c_reg[3] = cv.w;
        }
        ull hi = pack_bf4(hv.x, hv.y, hv.z, hv.w);
        float r0 = hv.x - __bfloat162float(__float2bfloat16_rn(hv.x));
        float r1 = hv.y - __bfloat162float(__float2bfloat16_rn(hv.y));
        float r2 = hv.z - __bfloat162float(__float2bfloat16_rn(hv.z));
        float r3 = hv.w - __bfloat162float(__float2bfloat16_rn(hv.w));
        ull lo = pack_bf4(r0, r1, r2, r3);
        *(ull*)&As[0][er * APL + kk]       = hi;
        *(ull*)&As[0][(er + 8) * APL + kk] = lo;
    }

    int bclamp = b0 + er; if (bclamp > BB - 1) bclamp = BB - 1;
    const float* xrow_e = xp + (size_t)bclamp * TT * GG;
    float* accw = &s_acc[wid][0];

    __syncthreads();

    for (int t = 0; t < TT; t++) {
        int cur = t & 1, nxt = cur ^ 1;

        // prefetch xproj for this step's cells
        float4 xpv[4];
        if (eact) {
#pragma unroll
            for (int g = 0; g < 4; g++)
                xpv[g] = *(const float4*)&xrow_e[(size_t)t * GG + g * 128 + kk];
        }

        // ---- MMA: acc[g] = A[16][128] @ B[128][gate-slice] ----
        wmma::fragment<wmma::accumulator, 16, 16, 16, float> acc[4];
#pragma unroll
        for (int g = 0; g < 4; g++) wmma::fill_fragment(acc[g], 0.0f);
#pragma unroll
        for (int ks = 0; ks < 8; ks++) {
            wmma::fragment<wmma::matrix_a, 16, 16, 16, __nv_bfloat16, wmma::row_major> af;
            wmma::load_matrix_sync(af, &As[cur][ks * 16], APL);
#pragma unroll
            for (int g = 0; g < 4; g++)
                wmma::mma_sync(acc[g], af, bf[g][ks], acc[g]);
        }
#pragma unroll
        for (int g = 0; g < 4; g++)
            wmma::store_matrix_sync(&accw[g * 16], acc[g], ACW, wmma::mem_row_major);
        __syncwarp();

        // ---- warp-local epilogue ----
        if (eact) {
            float gate[4][4];
#pragma unroll
            for (int g = 0; g < 4; g++) {
                float4 ahi = *(const float4*)&accw[er * ACW + g * 16 + kq];
                float4 alo = *(const float4*)&accw[(er + 8) * ACW + g * 16 + kq];
                float4 bg  = *(const float4*)&s_bias[g * 128 + kk];
                gate[g][0] = ahi.x + alo.x + bg.x + xpv[g].x;
                gate[g][1] = ahi.y + alo.y + bg.y + xpv[g].y;
                gate[g][2] = ahi.z + alo.z + bg.z + xpv[g].z;
                gate[g][3] = ahi.w + alo.w + bg.w + xpv[g].w;
            }
            float hn[4];
#pragma unroll
            for (int l = 0; l < 4; l++) {
                float iv = fsig(gate[0][l]);
                float fv = fsig(gate[1][l]);
                float gv = ftanh(gate[2][l]);
                float ov = fsig(gate[3][l]);
                c_reg[l] = fmaf(fv, c_reg[l], iv * gv);
                hn[l] = ov * ftanh(c_reg[l]);
            }
            ull hi = pack_bf4(hn[0], hn[1], hn[2], hn[3]);
            float r0 = hn[0] - __bfloat162float(__float2bfloat16_rn(hn[0]));
            float r1 = hn[1] - __bfloat162float(__float2bfloat16_rn(hn[1]));
            float r2 = hn[2] - __bfloat162float(__float2bfloat16_rn(hn[2]));
            float r3 = hn[3] - __bfloat162float(__float2bfloat16_rn(hn[3]));
            ull lo = pack_bf4(r0, r1, r2, r3);
            *(ull*)&As[nxt][er * APL + kk]       = hi;
            *(ull*)&As[nxt][(er + 8) * APL + kk] = lo;
            if (ewr)
                *(float4*)(out_enc + ((size_t)(b0 + er) * TT + t) * HH + kk) =
                    make_float4(hn[0], hn[1], hn[2], hn[3]);
        }
        __syncthreads();
    }
}

// ---------------------------------------------------------------------------
// Launch
// ---------------------------------------------------------------------------
extern "C" void kernel_launch(void* const* d_in, const int* in_sizes, int n_in,
                              void* d_out, int out_size) {
    const float* x      = (const float*)d_in[0];
    const float* attn_w = (const float*)d_in[1];
    const float* attn_b = (const float*)d_in[2];
    const float* w_ih   = (const float*)d_in[3];
    const float* w_hh   = (const float*)d_in[4];
    const float* b_ih   = (const float*)d_in[5];
    const float* b_hh   = (const float*)d_in[6];
    const float* h0     = (const float*)d_in[7];
    const float* c0     = (const float*)d_in[8];

    float* out      = (float*)d_out;
    float* out_attn = out;
    float* out_enc  = out + (size_t)BB * TT * NN;

    float* xproj;
    cudaGetSymbolAddress((void**)&xproj, g_xproj);

    cudaFuncSetAttribute(fused_attn_xproj_kernel,
                         cudaFuncAttributeMaxDynamicSharedMemorySize, XP_SMEM);

    setup_kernel<<<192, 256>>>(w_ih, w_hh, b_ih, b_hh);
    fused_attn_xproj_kernel<<<BB, 256, XP_SMEM>>>(x, attn_w, attn_b, out_attn, xproj);
    lstm_wmma_kernel<<<NBLK, 256>>>(xproj, h0, c0, out_enc);
}